// round 2
// baseline (speedup 1.0000x reference)
#include <cuda_runtime.h>
#include <cuda_bf16.h>
#include <cstdint>
#include <cstdio>

// Problem constants
#define PN   256      // num paths
#define LN   64       // max path length
#define ID   512      // input dim
#define HD   1024     // hidden dim
#define G4   4096     // 4*H
#define ODIM 2

// ---------------------------------------------------------------------------
// Scratch (device globals: allocation-free per harness rules)
// ---------------------------------------------------------------------------
__device__ __align__(16) float    g_xproj[(size_t)LN * PN * G4];   // [t][p][4H]  268 MB
__device__ __align__(16) float    g_hbuf[2][PN * HD];              // double-buffered h
__device__ __align__(16) float    g_ctx[PN * HD];
__device__ __align__(16) float    g_attn[PN * HD];
__device__ __align__(16) float    g_pooled[HD];
__device__ unsigned g_barcnt;

// ---------------------------------------------------------------------------
// Helpers
// ---------------------------------------------------------------------------
__device__ __forceinline__ uint32_t f2tf32(float x) {
    uint32_t u;
    asm("cvt.rna.tf32.f32 %0, %1;" : "=r"(u) : "f"(x));
    return u;
}

__device__ __forceinline__ void mma_tf32(float* c,
                                         uint32_t a0, uint32_t a1, uint32_t a2, uint32_t a3,
                                         uint32_t b0, uint32_t b1) {
    asm volatile(
        "mma.sync.aligned.m16n8k8.row.col.f32.tf32.tf32.f32 "
        "{%0,%1,%2,%3}, {%4,%5,%6,%7}, {%8,%9}, {%0,%1,%2,%3};\n"
        : "+f"(c[0]), "+f"(c[1]), "+f"(c[2]), "+f"(c[3])
        : "r"(a0), "r"(a1), "r"(a2), "r"(a3), "r"(b0), "r"(b1));
}

__device__ __forceinline__ float sigmoidf(float x) {
    return 1.0f / (1.0f + __expf(-x));
}

// ---------------------------------------------------------------------------
// Init: zero h buffer 0 and the grid-barrier counter (per-launch determinism)
// ---------------------------------------------------------------------------
__global__ void init_kernel() {
    int i = blockIdx.x * blockDim.x + threadIdx.x;
    if (i == 0) g_barcnt = 0u;
    if (i < PN * HD) g_hbuf[0][i] = 0.0f;
}

// ---------------------------------------------------------------------------
// Generic tf32 GEMM:  C[M,N] = A[M,K] @ B[N,K]^T (+bias)
// BM=BN=64, BK=16, 128 threads (4 warps as 2x2, each warp 32x32).
// gather!=0: A row m -> emb_table row paths[(m&255)*LN + (m>>8)]  (xproj layout [t][p])
// srcSel: 0=Aext  1=g_hbuf[0]  2=g_ctx      dstSel: 0=g_xproj 1=g_ctx 2=g_attn
// ---------------------------------------------------------------------------
__global__ __launch_bounds__(128)
void gemm_tf32(const float* __restrict__ Aext,
               const int*   __restrict__ paths,
               const float* __restrict__ B,
               const float* __restrict__ bias,
               int srcSel, int dstSel, int gather,
               int M, int N, int K)
{
    __shared__ uint32_t As[64][17];
    __shared__ uint32_t Bs[64][17];
    __shared__ const float* rowA[64];

    const int tid  = threadIdx.x;
    const int warp = tid >> 5, lane = tid & 31;
    const int wm = warp >> 1, wn = warp & 1;
    const int m0 = blockIdx.y * 64, n0 = blockIdx.x * 64;

    const float* A = Aext;
    if (srcSel == 1)      A = g_hbuf[0];
    else if (srcSel == 2) A = g_ctx;
    float* C = g_xproj;
    if (dstSel == 1)      C = g_ctx;
    else if (dstSel == 2) C = g_attn;

    float acc[2][4][4];
#pragma unroll
    for (int i = 0; i < 2; i++)
#pragma unroll
        for (int j = 0; j < 4; j++)
#pragma unroll
            for (int k = 0; k < 4; k++) acc[i][j][k] = 0.0f;

    if (tid < 64) {
        int mg = m0 + tid;
        const float* p;
        if (gather) {
            int pp = mg & 255, tt = mg >> 8;
            int tok = paths[pp * LN + tt];
            p = A + (size_t)tok * K;
        } else {
            p = A + (size_t)mg * K;
        }
        rowA[tid] = p;
    }
    __syncthreads();

    for (int k0 = 0; k0 < K; k0 += 16) {
        __syncthreads();
#pragma unroll
        for (int r = 0; r < 2; r++) {
            int e = tid + r * 128;         // 0..255 : 64 rows x 4 float4
            int row = e >> 2, c4 = e & 3;
            float4 v = *reinterpret_cast<const float4*>(rowA[row] + k0 + c4 * 4);
            As[row][c4 * 4 + 0] = f2tf32(v.x);
            As[row][c4 * 4 + 1] = f2tf32(v.y);
            As[row][c4 * 4 + 2] = f2tf32(v.z);
            As[row][c4 * 4 + 3] = f2tf32(v.w);
            float4 w = *reinterpret_cast<const float4*>(B + (size_t)(n0 + row) * K + k0 + c4 * 4);
            Bs[row][c4 * 4 + 0] = f2tf32(w.x);
            Bs[row][c4 * 4 + 1] = f2tf32(w.y);
            Bs[row][c4 * 4 + 2] = f2tf32(w.z);
            Bs[row][c4 * 4 + 3] = f2tf32(w.w);
        }
        __syncthreads();

#pragma unroll
        for (int kk = 0; kk < 16; kk += 8) {
            int kc = kk + (lane & 3);
            uint32_t a[2][4];
#pragma unroll
            for (int mi = 0; mi < 2; mi++) {
                int r = wm * 32 + mi * 16 + (lane >> 2);
                a[mi][0] = As[r][kc];
                a[mi][1] = As[r + 8][kc];
                a[mi][2] = As[r][kc + 4];
                a[mi][3] = As[r + 8][kc + 4];
            }
#pragma unroll
            for (int nj = 0; nj < 4; nj++) {
                int cn = wn * 32 + nj * 8 + (lane >> 2);
                uint32_t b0 = Bs[cn][kc], b1 = Bs[cn][kc + 4];
                mma_tf32(acc[0][nj], a[0][0], a[0][1], a[0][2], a[0][3], b0, b1);
                mma_tf32(acc[1][nj], a[1][0], a[1][1], a[1][2], a[1][3], b0, b1);
            }
        }
    }

#pragma unroll
    for (int mi = 0; mi < 2; mi++) {
        int row = m0 + wm * 32 + mi * 16 + (lane >> 2);
#pragma unroll
        for (int nj = 0; nj < 4; nj++) {
            int col = n0 + wn * 32 + nj * 8 + 2 * (lane & 3);
            float b0v = bias ? bias[col] : 0.0f;
            float b1v = bias ? bias[col + 1] : 0.0f;
            C[(size_t)row * N + col]           = acc[mi][nj][0] + b0v;
            C[(size_t)row * N + col + 1]       = acc[mi][nj][1] + b1v;
            C[(size_t)(row + 8) * N + col]     = acc[mi][nj][2] + b0v;
            C[(size_t)(row + 8) * N + col + 1] = acc[mi][nj][3] + b1v;
        }
    }
}

// ---------------------------------------------------------------------------
// Persistent LSTM recurrence. 128 blocks x 128 threads, single wave.
// Block b: p-rows [ (b>>5)*64 , +64 ), j-cols [ (b&31)*32 , +32 ), all 4 gates.
// c and h live in registers for the whole 64-step loop; h is published to a
// double-buffered global each step behind a hand-rolled grid barrier.
// ---------------------------------------------------------------------------
__global__ __launch_bounds__(128)
void lstm_kernel(const float* __restrict__ Whh,
                 const float* __restrict__ b_ih,
                 const float* __restrict__ b_hh,
                 const int*   __restrict__ lengths)
{
    __shared__ uint32_t Hs[64][33];
    __shared__ uint32_t Ws[128][33];

    const int tid = threadIdx.x, warp = tid >> 5, lane = tid & 31;
    const int mtile = blockIdx.x >> 5;
    const int jtile = blockIdx.x & 31;
    const int pbase = mtile * 64;

    const int r0  = warp * 16 + (lane >> 2);     // block-local row of this thread
    const int p0g = pbase + r0, p1g = p0g + 8;
    const int len0 = lengths[p0g], len1 = lengths[p1g];

    float c_reg[2][8], h_reg[2][8];
#pragma unroll
    for (int i = 0; i < 2; i++)
#pragma unroll
        for (int j = 0; j < 8; j++) { c_reg[i][j] = 0.0f; h_reg[i][j] = 0.0f; }

    for (int t = 0; t < LN; t++) {
        const float* hin  = g_hbuf[t & 1];
        float*       hout = g_hbuf[(t + 1) & 1];

        float acc[16][4];
#pragma unroll
        for (int i = 0; i < 16; i++)
#pragma unroll
            for (int j = 0; j < 4; j++) acc[i][j] = 0.0f;

        for (int k0 = 0; k0 < HD; k0 += 32) {
            __syncthreads();
            // h tile: 64 rows x 32 k  (L2 via ldcg: cross-SM coherence)
#pragma unroll
            for (int r = 0; r < 4; r++) {
                int e = tid + r * 128;            // 0..511
                int row = e >> 3, c4 = e & 7;
                float4 v = __ldcg(reinterpret_cast<const float4*>(
                    hin + (size_t)(pbase + row) * HD + k0 + c4 * 4));
                Hs[row][c4 * 4 + 0] = f2tf32(v.x);
                Hs[row][c4 * 4 + 1] = f2tf32(v.y);
                Hs[row][c4 * 4 + 2] = f2tf32(v.z);
                Hs[row][c4 * 4 + 3] = f2tf32(v.w);
            }
            // W tile: 128 cols (4 gates x 32 j) x 32 k
#pragma unroll
            for (int r = 0; r < 8; r++) {
                int e = tid + r * 128;            // 0..1023
                int row = e >> 3, c4 = e & 7;
                int g = row >> 5, jj = row & 31;
                float4 v = *reinterpret_cast<const float4*>(
                    Whh + (size_t)(g * HD + jtile * 32 + jj) * HD + k0 + c4 * 4);
                Ws[row][c4 * 4 + 0] = f2tf32(v.x);
                Ws[row][c4 * 4 + 1] = f2tf32(v.y);
                Ws[row][c4 * 4 + 2] = f2tf32(v.z);
                Ws[row][c4 * 4 + 3] = f2tf32(v.w);
            }
            __syncthreads();

#pragma unroll
            for (int kk = 0; kk < 32; kk += 8) {
                int kc = kk + (lane & 3);
                int ar = warp * 16 + (lane >> 2);
                uint32_t a0 = Hs[ar][kc],     a1 = Hs[ar + 8][kc];
                uint32_t a2 = Hs[ar][kc + 4], a3 = Hs[ar + 8][kc + 4];
#pragma unroll
                for (int nf = 0; nf < 16; nf++) {
                    int cn = nf * 8 + (lane >> 2);
                    uint32_t b0 = Ws[cn][kc], b1 = Ws[cn][kc + 4];
                    mma_tf32(acc[nf], a0, a1, a2, a3, b0, b1);
                }
            }
        }

        // Epilogue: gates -> (c,h) in registers; publish h (frozen paths re-publish old h)
        const float* xp = g_xproj + (size_t)t * PN * G4;
#pragma unroll
        for (int rr = 0; rr < 2; rr++) {
            int p   = rr ? p1g : p0g;
            int len = rr ? len1 : len0;
            const float* xrow = xp + (size_t)p * G4;
#pragma unroll
            for (int nj = 0; nj < 4; nj++) {
#pragma unroll
                for (int e = 0; e < 2; e++) {
                    int jg = jtile * 32 + nj * 8 + 2 * (lane & 3) + e;
                    int ci = rr * 2 + e;
                    if (t < len) {
                        float gi = acc[nj][ci]      + xrow[jg]        + b_ih[jg]        + b_hh[jg];
                        float gf = acc[4 + nj][ci]  + xrow[HD + jg]   + b_ih[HD + jg]   + b_hh[HD + jg];
                        float gg = acc[8 + nj][ci]  + xrow[2*HD + jg] + b_ih[2*HD + jg] + b_hh[2*HD + jg];
                        float go = acc[12 + nj][ci] + xrow[3*HD + jg] + b_ih[3*HD + jg] + b_hh[3*HD + jg];
                        float cn = sigmoidf(gf) * c_reg[rr][nj * 2 + e] + sigmoidf(gi) * tanhf(gg);
                        c_reg[rr][nj * 2 + e] = cn;
                        h_reg[rr][nj * 2 + e] = sigmoidf(go) * tanhf(cn);
                    }
                    hout[(size_t)p * HD + jg] = h_reg[rr][nj * 2 + e];
                }
            }
        }

        // Grid barrier (release: st + fence + barrier + atom; acquire: volatile spin + fence)
        __threadfence();
        __syncthreads();
        if (tid == 0) {
            atomicAdd(&g_barcnt, 1u);
            unsigned target = (unsigned)(t + 1) * (unsigned)gridDim.x;
            volatile unsigned* vp = &g_barcnt;
            while (*vp < target) __nanosleep(64);
            __threadfence();
        }
        __syncthreads();
    }
}

// ---------------------------------------------------------------------------
// Maxpool over the P paths
// ---------------------------------------------------------------------------
__global__ void pool_kernel() {
    int j = blockIdx.x * blockDim.x + threadIdx.x;   // grid 8 x 128 = 1024
    float m = -3.402823466e+38f;
#pragma unroll 4
    for (int p = 0; p < PN; p++) m = fmaxf(m, g_attn[p * HD + j]);
    g_pooled[j] = m;
}

// ---------------------------------------------------------------------------
// Final linear + sigmoid
// ---------------------------------------------------------------------------
__global__ void final_kernel(const float* __restrict__ Wlin,
                             const float* __restrict__ blin,
                             float* __restrict__ out)
{
    __shared__ float red0[8], red1[8];
    int tid = threadIdx.x;                      // 256 threads
    float s0 = 0.0f, s1 = 0.0f;
    for (int j = tid; j < HD; j += 256) {
        float pv = g_pooled[j];
        s0 += pv * Wlin[j];
        s1 += pv * Wlin[HD + j];
    }
#pragma unroll
    for (int o = 16; o; o >>= 1) {
        s0 += __shfl_xor_sync(0xFFFFFFFFu, s0, o);
        s1 += __shfl_xor_sync(0xFFFFFFFFu, s1, o);
    }
    if ((tid & 31) == 0) { red0[tid >> 5] = s0; red1[tid >> 5] = s1; }
    __syncthreads();
    if (tid == 0) {
        float z0 = blin[0], z1 = blin[1];
#pragma unroll
        for (int w = 0; w < 8; w++) { z0 += red0[w]; z1 += red1[w]; }
        out[0] = 1.0f / (1.0f + expf(-z0));
        out[1] = 1.0f / (1.0f + expf(-z1));
    }
}

// ---------------------------------------------------------------------------
// Launch
// ---------------------------------------------------------------------------
extern "C" void kernel_launch(void* const* d_in, const int* in_sizes, int n_in,
                              void* d_out, int out_size)
{
    (void)in_sizes; (void)n_in; (void)out_size;
    const int*   paths   = (const int*)  d_in[0];
    const int*   lengths = (const int*)  d_in[1];
    const float* emb     = (const float*)d_in[2];
    const float* W_ih    = (const float*)d_in[3];
    const float* W_hh    = (const float*)d_in[4];
    const float* b_ih    = (const float*)d_in[5];
    const float* b_hh    = (const float*)d_in[6];
    const float* W_in    = (const float*)d_in[7];
    const float* b_in    = (const float*)d_in[8];
    const float* W_out   = (const float*)d_in[9];
    const float* b_out   = (const float*)d_in[10];
    const float* W_lin   = (const float*)d_in[11];
    const float* b_lin   = (const float*)d_in[12];
    float* out = (float*)d_out;

    // reset h0 + barrier counter (determinism across graph replays)
    init_kernel<<<1024, 256>>>();

    // x-projection for all (t,p): xproj = gather(emb)[16384,512] @ W_ih^T -> [t][p][4096]
    gemm_tf32<<<dim3(G4 / 64, (PN * LN) / 64), 128>>>(
        emb, paths, W_ih, nullptr, /*src*/0, /*dst*/0, /*gather*/1,
        PN * LN, G4, ID);

    // 64-step recurrence (persistent, grid-barriered); final_h lands in g_hbuf[0]
    lstm_kernel<<<128, 128>>>(W_hh, b_ih, b_hh, lengths);

    // attention collapses (softmax over 1 element == 1):
    // ctx = final_h @ W_v^T + b_v   (W_v = rows [2H,3H) of in_proj)
    gemm_tf32<<<dim3(HD / 64, PN / 64), 128>>>(
        nullptr, nullptr, W_in + (size_t)2 * HD * HD, b_in + 2 * HD,
        /*src*/1, /*dst*/1, /*gather*/0, PN, HD, HD);

    // attn_out = ctx @ W_out^T + b_out
    gemm_tf32<<<dim3(HD / 64, PN / 64), 128>>>(
        nullptr, nullptr, W_out, b_out,
        /*src*/2, /*dst*/2, /*gather*/0, PN, HD, HD);

    pool_kernel<<<8, 128>>>();
    final_kernel<<<1, 256>>>(W_lin, b_lin, out);
}

// round 6
// speedup vs baseline: 3.6980x; 3.6980x over previous
#include <cuda_runtime.h>
#include <cuda_bf16.h>
#include <cstdint>

// Problem constants
#define PN   256      // num paths
#define LN   64       // max path length
#define ID   512      // input dim
#define HD   1024     // hidden dim
#define G4   4096     // 4*H

// ---------------------------------------------------------------------------
// Scratch (device globals; allocation-free). NEVER passed from host code —
// all selection happens inside kernels (host-side &devglobal is invalid).
// ---------------------------------------------------------------------------
__device__ __align__(16) __nv_bfloat16 g_x[(size_t)LN * PN * ID];      // gathered emb (sorted p)
__device__ __align__(16) __nv_bfloat16 g_xproj[(size_t)LN * PN * G4];  // [t][ps][4H]
__device__ __align__(16) __nv_bfloat16 g_wih[G4 * ID];
__device__ __align__(16) __nv_bfloat16 g_whh[G4 * HD];
__device__ __align__(16) __nv_bfloat16 g_wv[HD * HD];
__device__ __align__(16) __nv_bfloat16 g_wo[HD * HD];
__device__ __align__(16) __nv_bfloat16 g_h[2][PN * HD];                // double-buffered h (bf16)
__device__ __align__(16) __nv_bfloat16 g_hfin[PN * HD];                // final h per path
__device__ __align__(16) float         g_c[PN * HD];                   // cell state fp32
__device__ __align__(16) __nv_bfloat16 g_ctx[PN * HD];
__device__ __align__(16) float         g_attn[PN * HD];
__device__ __align__(16) float         g_bias[G4];                     // b_ih + b_hh
__device__ __align__(16) float         g_pooled[HD];
__device__ int g_perm[PN];
__device__ int g_slen[PN];       // sorted lengths (desc)
__device__ int g_activeM[LN];    // #paths with len > t

// ---------------------------------------------------------------------------
// Helpers
// ---------------------------------------------------------------------------
__device__ __forceinline__ uint32_t cvta_s(const void* p) {
    return (uint32_t)__cvta_generic_to_shared(p);
}
__device__ __forceinline__ void cp_ca16(uint32_t d, const void* s) {
    asm volatile("cp.async.ca.shared.global [%0],[%1],16;\n" :: "r"(d), "l"(s));
}
__device__ __forceinline__ void cp_commit() { asm volatile("cp.async.commit_group;\n"); }
__device__ __forceinline__ void cp_wait0()  { asm volatile("cp.async.wait_group 0;\n"); }
__device__ __forceinline__ void cp_wait1()  { asm volatile("cp.async.wait_group 1;\n"); }

__device__ __forceinline__ void mma_bf16(float* c,
                                         uint32_t a0, uint32_t a1, uint32_t a2, uint32_t a3,
                                         uint32_t b0, uint32_t b1) {
    asm volatile(
        "mma.sync.aligned.m16n8k16.row.col.f32.bf16.bf16.f32 "
        "{%0,%1,%2,%3}, {%4,%5,%6,%7}, {%8,%9}, {%0,%1,%2,%3};\n"
        : "+f"(c[0]), "+f"(c[1]), "+f"(c[2]), "+f"(c[3])
        : "r"(a0), "r"(a1), "r"(a2), "r"(a3), "r"(b0), "r"(b1));
}

__device__ __forceinline__ uint32_t packbf2(float lo, float hi) {
    uint32_t r;
    asm("cvt.rn.bf16x2.f32 %0, %1, %2;\n" : "=r"(r) : "f"(hi), "f"(lo));
    return r;
}
__device__ __forceinline__ float bflo(uint32_t u) { return __uint_as_float(u << 16); }
__device__ __forceinline__ float bfhi(uint32_t u) { return __uint_as_float(u & 0xFFFF0000u); }

__device__ __forceinline__ float fast_tanh(float x) {
    float y; asm("tanh.approx.f32 %0,%1;\n" : "=f"(y) : "f"(x)); return y;
}
__device__ __forceinline__ float fsig(float x) { return 0.5f * fast_tanh(0.5f * x) + 0.5f; }

// ---------------------------------------------------------------------------
// zero: g_c (65536 uint4) and g_h[0] (32768 uint4). grid 384 x 256.
// ---------------------------------------------------------------------------
__global__ void zero_kernel() {
    int i = blockIdx.x * 256 + threadIdx.x;
    uint4 z = make_uint4(0u, 0u, 0u, 0u);
    if (i < 65536)       reinterpret_cast<uint4*>(g_c)[i] = z;
    else if (i < 98304)  reinterpret_cast<uint4*>(g_h[0])[i - 65536] = z;
}

// ---------------------------------------------------------------------------
// Sort paths by length (desc) via counting sort; scratch in SHARED memory
// (no thread-local arrays -> no local-mem pool growth).
// ---------------------------------------------------------------------------
__global__ void sort_kernel(const int* __restrict__ lengths) {
    __shared__ int s_cnt[LN + 1];
    __shared__ int s_start[LN + 1];
    int tid = threadIdx.x;  // 256
    if (tid <= LN) s_cnt[tid] = 0;
    __syncthreads();
    if (tid < PN) atomicAdd(&s_cnt[lengths[tid]], 1);
    __syncthreads();
    if (tid == 0) {
        int run = 0;
        for (int l = LN; l >= 1; l--) { s_start[l] = run; run += s_cnt[l]; }
        for (int p = 0; p < PN; p++) { int l = lengths[p]; g_perm[s_start[l]++] = p; }
    }
    __syncthreads();
    if (tid < PN) g_slen[tid] = lengths[g_perm[tid]];
    if (tid < LN) {
        int a = 0;
        for (int l = tid + 1; l <= LN; l++) a += s_cnt[l];
        g_activeM[tid] = a;
    }
}

// ---------------------------------------------------------------------------
// fp32 -> bf16 weight conversion. dstSel: 0=g_wih 1=g_whh 2=g_wv 3=g_wo
// ---------------------------------------------------------------------------
__global__ void cvt_kernel(const float* __restrict__ src, int dstSel, int n) {
    __nv_bfloat16* dst = g_wih;
    if (dstSel == 1) dst = g_whh;
    else if (dstSel == 2) dst = g_wv;
    else if (dstSel == 3) dst = g_wo;
    int i = (blockIdx.x * blockDim.x + threadIdx.x) * 4;
    if (i >= n) return;
    float4 v = *reinterpret_cast<const float4*>(src + i);
    *reinterpret_cast<uint2*>(dst + i) = make_uint2(packbf2(v.x, v.y), packbf2(v.z, v.w));
}

__global__ void bias_kernel(const float* __restrict__ b_ih, const float* __restrict__ b_hh) {
    int i = blockIdx.x * blockDim.x + threadIdx.x;
    if (i < G4) g_bias[i] = b_ih[i] + b_hh[i];
}

// ---------------------------------------------------------------------------
// Gather + convert: g_x[m = t*256+ps] = bf16(emb[paths[perm[ps]*64 + t]])
// ---------------------------------------------------------------------------
__global__ void gather_kernel(const int* __restrict__ paths, const float* __restrict__ emb) {
    int m = blockIdx.x;
    int t = m >> 8, ps = m & 255;
    if (t >= g_slen[ps]) return;
    int tok = paths[g_perm[ps] * LN + t];
    const float4* src = reinterpret_cast<const float4*>(emb + (size_t)tok * ID);
    int tid = threadIdx.x;   // 64
    float4 v0 = src[tid * 2], v1 = src[tid * 2 + 1];
    uint4 o;
    o.x = packbf2(v0.x, v0.y); o.y = packbf2(v0.z, v0.w);
    o.z = packbf2(v1.x, v1.y); o.w = packbf2(v1.z, v1.w);
    reinterpret_cast<uint4*>(g_x + (size_t)m * ID)[tid] = o;
}

// ---------------------------------------------------------------------------
// bf16 GEMM: C[M,N] = A[M,K] @ B[N,K]^T (+bias). BM=128 BN=64 BK=32, 256 thr.
// selA: 0=g_x 1=g_hfin 2=g_ctx ; selB: 0=g_wih 1=g_wv 2=g_wo
// selC: 0=g_xproj(bf16) 1=g_ctx(bf16) 2=g_attn(f32)
// skipMode: use g_activeM to skip dead [t][ps] tiles (xproj layout).
// ---------------------------------------------------------------------------
__global__ __launch_bounds__(256)
void gemm_bf16(const float* __restrict__ bias,
               int selA, int selB, int selC, int skipMode,
               int M, int N, int K)
{
    __shared__ uint32_t As[2][128 * 20];
    __shared__ uint32_t Bs[2][64 * 20];

    const int tid = threadIdx.x, warp = tid >> 5, lane = tid & 31;
    const int wm = warp >> 1, wn = warp & 1;
    const int m0 = blockIdx.y * 128, n0 = blockIdx.x * 64;

    if (skipMode) {
        int t = m0 >> 8, ps0 = m0 & 255;
        if (g_activeM[t] <= ps0) return;
    }

    const __nv_bfloat16* A = g_x;
    if (selA == 1) A = g_hfin;
    else if (selA == 2) A = g_ctx;
    const __nv_bfloat16* B = g_wih;
    if (selB == 1) B = g_wv;
    else if (selB == 2) B = g_wo;

    float acc[2][4][4];
#pragma unroll
    for (int i = 0; i < 2; i++)
#pragma unroll
        for (int j = 0; j < 4; j++)
#pragma unroll
            for (int q = 0; q < 4; q++) acc[i][j][q] = 0.0f;

    const int nk = K >> 5;
    uint32_t asb[2] = {cvta_s(As[0]), cvta_s(As[1])};
    uint32_t bsb[2] = {cvta_s(Bs[0]), cvta_s(Bs[1])};
    const int lrow = tid >> 2, lc = tid & 3;

    {   // prologue stage 0
        cp_ca16(asb[0] + (lrow * 20 + lc * 4) * 4,        A + (size_t)(m0 + lrow) * K + lc * 8);
        cp_ca16(asb[0] + ((lrow + 64) * 20 + lc * 4) * 4, A + (size_t)(m0 + lrow + 64) * K + lc * 8);
        cp_ca16(bsb[0] + (lrow * 20 + lc * 4) * 4,        B + (size_t)(n0 + lrow) * K + lc * 8);
        cp_commit();
    }

    for (int kt = 0; kt < nk; kt++) {
        if (kt + 1 < nk) {
            int s = (kt + 1) & 1, k0 = (kt + 1) * 32;
            cp_ca16(asb[s] + (lrow * 20 + lc * 4) * 4,        A + (size_t)(m0 + lrow) * K + k0 + lc * 8);
            cp_ca16(asb[s] + ((lrow + 64) * 20 + lc * 4) * 4, A + (size_t)(m0 + lrow + 64) * K + k0 + lc * 8);
            cp_ca16(bsb[s] + (lrow * 20 + lc * 4) * 4,        B + (size_t)(n0 + lrow) * K + k0 + lc * 8);
            cp_commit();
            cp_wait1();
        } else {
            cp_wait0();
        }
        __syncthreads();

        const uint32_t* as = As[kt & 1];
        const uint32_t* bs = Bs[kt & 1];
#pragma unroll
        for (int ks = 0; ks < 2; ks++) {
            int kw = ks * 8 + (lane & 3);
            uint32_t a0[2], a1[2], a2[2], a3[2];
#pragma unroll
            for (int mi = 0; mi < 2; mi++) {
                int r = wm * 32 + mi * 16 + (lane >> 2);
                a0[mi] = as[r * 20 + kw];
                a1[mi] = as[(r + 8) * 20 + kw];
                a2[mi] = as[r * 20 + kw + 4];
                a3[mi] = as[(r + 8) * 20 + kw + 4];
            }
#pragma unroll
            for (int nj = 0; nj < 4; nj++) {
                int cn = wn * 32 + nj * 8 + (lane >> 2);
                uint32_t b0 = bs[cn * 20 + kw], b1 = bs[cn * 20 + kw + 4];
                mma_bf16(acc[0][nj], a0[0], a1[0], a2[0], a3[0], b0, b1);
                mma_bf16(acc[1][nj], a0[1], a1[1], a2[1], a3[1], b0, b1);
            }
        }
        __syncthreads();
    }

#pragma unroll
    for (int mi = 0; mi < 2; mi++) {
#pragma unroll
        for (int half = 0; half < 2; half++) {
            int row = m0 + wm * 32 + mi * 16 + (lane >> 2) + half * 8;
#pragma unroll
            for (int nj = 0; nj < 4; nj++) {
                int col = n0 + wn * 32 + nj * 8 + 2 * (lane & 3);
                float v0 = acc[mi][nj][half * 2];
                float v1 = acc[mi][nj][half * 2 + 1];
                if (bias) { v0 += bias[col]; v1 += bias[col + 1]; }
                if (selC == 2) {
                    g_attn[(size_t)row * N + col]     = v0;
                    g_attn[(size_t)row * N + col + 1] = v1;
                } else {
                    __nv_bfloat16* C = (selC == 0) ? g_xproj : g_ctx;
                    *reinterpret_cast<uint32_t*>(C + (size_t)row * N + col) = packbf2(v0, v1);
                }
            }
        }
    }
}

// ---------------------------------------------------------------------------
// One LSTM time step. Grid (32 jtiles, 4 ptiles) x 256 threads.
// Block: 64 p-rows x 32 j-cols x 4 gates (N=128 gate-cols), K=1024.
// gates = h @ Whh^T via mma; pointwise via smem exchange; c fp32 in global,
// h bf16 double-buffered. No inter-block sync needed within a step.
// ---------------------------------------------------------------------------
__global__ __launch_bounds__(256)
void lstm_step_kernel(int t)
{
    __shared__ uint32_t SM[8448];     // union: pipeline (7680 w) | gates 64x132 f32
    const int activeM = g_activeM[t];
    const int pbase = blockIdx.y * 64;
    if (pbase >= activeM) return;
    const int jb = blockIdx.x;                    // j-tile [jb*32, +32)
    const int tid = threadIdx.x, warp = tid >> 5, lane = tid & 31;
    const int wm = warp >> 2, wn = warp & 3;      // 2 x 4 warps, warp tile 32x32
    const __nv_bfloat16* hin = g_h[t & 1];

    uint32_t asb[2] = {cvta_s(SM), cvta_s(SM + 1280)};          // H: 64 x 20 words
    uint32_t bsb[2] = {cvta_s(SM + 2560), cvta_s(SM + 5120)};   // W: 128 x 20 words

    float acc[2][4][4];
#pragma unroll
    for (int i = 0; i < 2; i++)
#pragma unroll
        for (int j = 0; j < 4; j++)
#pragma unroll
            for (int q = 0; q < 4; q++) acc[i][j][q] = 0.0f;

    const int arow = tid >> 2, ach = tid & 3;     // H tile: 64 rows x 4 x 16B

    {   // prologue k0 = 0
        cp_ca16(asb[0] + (arow * 20 + ach * 4) * 4, hin + (size_t)(pbase + arow) * HD + ach * 8);
#pragma unroll
        for (int i = 0; i < 2; i++) {
            int e = tid + i * 256, c = e >> 2, ch = e & 3;
            int wr = (c >> 5) * HD + jb * 32 + (c & 31);
            cp_ca16(bsb[0] + (c * 20 + ch * 4) * 4, g_whh + (size_t)wr * HD + ch * 8);
        }
        cp_commit();
    }

    for (int kt = 0; kt < 32; kt++) {
        if (kt + 1 < 32) {
            int s = (kt + 1) & 1, k0 = (kt + 1) * 32;
            cp_ca16(asb[s] + (arow * 20 + ach * 4) * 4,
                    hin + (size_t)(pbase + arow) * HD + k0 + ach * 8);
#pragma unroll
            for (int i = 0; i < 2; i++) {
                int e = tid + i * 256, c = e >> 2, ch = e & 3;
                int wr = (c >> 5) * HD + jb * 32 + (c & 31);
                cp_ca16(bsb[s] + (c * 20 + ch * 4) * 4, g_whh + (size_t)wr * HD + k0 + ch * 8);
            }
            cp_commit();
            cp_wait1();
        } else {
            cp_wait0();
        }
        __syncthreads();

        const uint32_t* as = SM + (kt & 1) * 1280;
        const uint32_t* bs = SM + 2560 + (kt & 1) * 2560;
#pragma unroll
        for (int ks = 0; ks < 2; ks++) {
            int kw = ks * 8 + (lane & 3);
            uint32_t a0[2], a1[2], a2[2], a3[2];
#pragma unroll
            for (int mi = 0; mi < 2; mi++) {
                int r = wm * 32 + mi * 16 + (lane >> 2);
                a0[mi] = as[r * 20 + kw];
                a1[mi] = as[(r + 8) * 20 + kw];
                a2[mi] = as[r * 20 + kw + 4];
                a3[mi] = as[(r + 8) * 20 + kw + 4];
            }
#pragma unroll
            for (int nj = 0; nj < 4; nj++) {
                int cn = wn * 32 + nj * 8 + (lane >> 2);
                uint32_t b0 = bs[cn * 20 + kw], b1 = bs[cn * 20 + kw + 4];
                mma_bf16(acc[0][nj], a0[0], a1[0], a2[0], a3[0], b0, b1);
                mma_bf16(acc[1][nj], a0[1], a1[1], a2[1], a3[1], b0, b1);
            }
        }
        __syncthreads();
    }

    // gates tile to smem (reuse SM as 64 x 132 floats)
    float* gsm = (float*)SM;
#pragma unroll
    for (int mi = 0; mi < 2; mi++)
#pragma unroll
        for (int half = 0; half < 2; half++) {
            int row = wm * 32 + mi * 16 + (lane >> 2) + half * 8;
#pragma unroll
            for (int nj = 0; nj < 4; nj++) {
                int col = wn * 32 + nj * 8 + 2 * (lane & 3);
                gsm[row * 132 + col]     = acc[mi][nj][half * 2];
                gsm[row * 132 + col + 1] = acc[mi][nj][half * 2 + 1];
            }
        }
    __syncthreads();

    // pointwise: thread -> p-row (tid>>2), 8 j's ((tid&3)*8)
    const int pl = tid >> 2;
    const int p  = pbase + pl;
    const int len = g_slen[p];
    if (t < len) {
        const int jloc = (tid & 3) * 8;
        const int jg = jb * 32 + jloc;
        const __nv_bfloat16* xrow = g_xproj + (size_t)t * PN * G4 + (size_t)p * G4;
        float gate[4][8];
#pragma unroll
        for (int g = 0; g < 4; g++) {
            uint4 xv = *reinterpret_cast<const uint4*>(xrow + g * HD + jg);
            float xb[8] = { bflo(xv.x), bfhi(xv.x), bflo(xv.y), bfhi(xv.y),
                            bflo(xv.z), bfhi(xv.z), bflo(xv.w), bfhi(xv.w) };
            float4 bv0 = *reinterpret_cast<const float4*>(g_bias + g * HD + jg);
            float4 bv1 = *reinterpret_cast<const float4*>(g_bias + g * HD + jg + 4);
            float bb[8] = { bv0.x, bv0.y, bv0.z, bv0.w, bv1.x, bv1.y, bv1.z, bv1.w };
#pragma unroll
            for (int e = 0; e < 8; e++)
                gate[g][e] = gsm[pl * 132 + g * 32 + jloc + e] + xb[e] + bb[e];
        }
        float4 c0 = *reinterpret_cast<const float4*>(g_c + (size_t)p * HD + jg);
        float4 c1 = *reinterpret_cast<const float4*>(g_c + (size_t)p * HD + jg + 4);
        float cc[8] = { c0.x, c0.y, c0.z, c0.w, c1.x, c1.y, c1.z, c1.w };
        float hh[8];
#pragma unroll
        for (int e = 0; e < 8; e++) {
            float cn = fsig(gate[1][e]) * cc[e] + fsig(gate[0][e]) * fast_tanh(gate[2][e]);
            cc[e] = cn;
            hh[e] = fsig(gate[3][e]) * fast_tanh(cn);
        }
        *reinterpret_cast<float4*>(g_c + (size_t)p * HD + jg)     = make_float4(cc[0], cc[1], cc[2], cc[3]);
        *reinterpret_cast<float4*>(g_c + (size_t)p * HD + jg + 4) = make_float4(cc[4], cc[5], cc[6], cc[7]);
        uint4 hp;
        hp.x = packbf2(hh[0], hh[1]); hp.y = packbf2(hh[2], hh[3]);
        hp.z = packbf2(hh[4], hh[5]); hp.w = packbf2(hh[6], hh[7]);
        *reinterpret_cast<uint4*>(g_h[(t + 1) & 1] + (size_t)p * HD + jg) = hp;
    }
}

// ---------------------------------------------------------------------------
// Collect final h per path from the parity buffer g_h[len & 1]
// ---------------------------------------------------------------------------
__global__ void collect_kernel() {
    int p = blockIdx.x;                        // 256 blocks x 128 threads
    int parity = g_slen[p] & 1;
    const uint4* src = reinterpret_cast<const uint4*>(g_h[parity] + (size_t)p * HD);
    uint4* dst = reinterpret_cast<uint4*>(g_hfin + (size_t)p * HD);
    dst[threadIdx.x] = src[threadIdx.x];
}

// ---------------------------------------------------------------------------
// Maxpool over paths (permutation-invariant)
// ---------------------------------------------------------------------------
__global__ void pool_kernel() {
    int j = blockIdx.x * blockDim.x + threadIdx.x;   // 8 x 128
    float m = -3.402823466e+38f;
#pragma unroll 4
    for (int p = 0; p < PN; p++) m = fmaxf(m, g_attn[p * HD + j]);
    g_pooled[j] = m;
}

// ---------------------------------------------------------------------------
// Final linear + sigmoid
// ---------------------------------------------------------------------------
__global__ void final_kernel(const float* __restrict__ Wlin,
                             const float* __restrict__ blin,
                             float* __restrict__ out)
{
    __shared__ float red0[8], red1[8];
    int tid = threadIdx.x;                      // 256
    float s0 = 0.0f, s1 = 0.0f;
    for (int j = tid; j < HD; j += 256) {
        float pv = g_pooled[j];
        s0 += pv * Wlin[j];
        s1 += pv * Wlin[HD + j];
    }
#pragma unroll
    for (int o = 16; o; o >>= 1) {
        s0 += __shfl_xor_sync(0xFFFFFFFFu, s0, o);
        s1 += __shfl_xor_sync(0xFFFFFFFFu, s1, o);
    }
    if ((tid & 31) == 0) { red0[tid >> 5] = s0; red1[tid >> 5] = s1; }
    __syncthreads();
    if (tid == 0) {
        float z0 = blin[0], z1 = blin[1];
#pragma unroll
        for (int w = 0; w < 8; w++) { z0 += red0[w]; z1 += red1[w]; }
        out[0] = 1.0f / (1.0f + expf(-z0));
        out[1] = 1.0f / (1.0f + expf(-z1));
    }
}

// ---------------------------------------------------------------------------
// Launch (only harness pointers cross the host/device boundary)
// ---------------------------------------------------------------------------
extern "C" void kernel_launch(void* const* d_in, const int* in_sizes, int n_in,
                              void* d_out, int out_size)
{
    (void)in_sizes; (void)n_in; (void)out_size;
    const int*   paths   = (const int*)  d_in[0];
    const int*   lengths = (const int*)  d_in[1];
    const float* emb     = (const float*)d_in[2];
    const float* W_ih    = (const float*)d_in[3];
    const float* W_hh    = (const float*)d_in[4];
    const float* b_ih    = (const float*)d_in[5];
    const float* b_hh    = (const float*)d_in[6];
    const float* W_in    = (const float*)d_in[7];
    const float* b_in    = (const float*)d_in[8];
    const float* W_out   = (const float*)d_in[9];
    const float* b_out   = (const float*)d_in[10];
    const float* W_lin   = (const float*)d_in[11];
    const float* b_lin   = (const float*)d_in[12];
    float* out = (float*)d_out;

    zero_kernel<<<384, 256>>>();
    sort_kernel<<<1, 256>>>(lengths);

    cvt_kernel<<<(G4 * ID / 4 + 255) / 256, 256>>>(W_ih, 0, G4 * ID);
    cvt_kernel<<<(G4 * HD / 4 + 255) / 256, 256>>>(W_hh, 1, G4 * HD);
    cvt_kernel<<<(HD * HD / 4 + 255) / 256, 256>>>(W_in + (size_t)2 * HD * HD, 2, HD * HD);
    cvt_kernel<<<(HD * HD / 4 + 255) / 256, 256>>>(W_out, 3, HD * HD);
    bias_kernel<<<G4 / 256, 256>>>(b_ih, b_hh);

    gather_kernel<<<LN * PN, 64>>>(paths, emb);

    // xproj = gathered_x @ W_ih^T -> bf16 [t][ps][4H], dead tiles skipped
    gemm_bf16<<<dim3(G4 / 64, (PN * LN) / 128), 256>>>(
        nullptr, /*selA*/0, /*selB*/0, /*selC*/0, /*skip*/1, PN * LN, G4, ID);

    // 64 recurrence steps (per-step launches; no grid barrier anywhere)
    for (int t = 0; t < LN; t++)
        lstm_step_kernel<<<dim3(32, 4), 256>>>(t);

    collect_kernel<<<PN, 128>>>();

    // attention collapses (softmax over length-1 axis == 1):
    // ctx = final_h @ W_v^T + b_v ; attn = ctx @ W_out^T + b_out
    gemm_bf16<<<dim3(HD / 64, PN / 128), 256>>>(
        b_in + 2 * HD, /*selA*/1, /*selB*/1, /*selC*/1, /*skip*/0, PN, HD, HD);
    gemm_bf16<<<dim3(HD / 64, PN / 128), 256>>>(
        b_out, /*selA*/2, /*selB*/2, /*selC*/2, /*skip*/0, PN, HD, HD);

    pool_kernel<<<8, 128>>>();
    final_kernel<<<1, 256>>>(W_lin, b_lin, out);
}

// round 7
// speedup vs baseline: 3.7645x; 1.0180x over previous
#include <cuda_runtime.h>
#include <cuda_bf16.h>
#include <cstdint>

// Problem constants
#define PN   256      // num paths
#define LN   64       // max path length
#define ID   512      // input dim
#define HD   1024     // hidden dim
#define G4   4096     // 4*H

// ---------------------------------------------------------------------------
// Scratch (device globals; allocation-free). NEVER passed from host code —
// all selection happens inside kernels (host-side &devglobal is invalid).
// ---------------------------------------------------------------------------
__device__ __align__(16) __nv_bfloat16 g_x[(size_t)LN * PN * ID];      // gathered emb (sorted p)
__device__ __align__(16) __nv_bfloat16 g_xproj[(size_t)LN * PN * G4];  // [t][ps][4H]
__device__ __align__(16) __nv_bfloat16 g_wih[G4 * ID];
__device__ __align__(16) __nv_bfloat16 g_whh[G4 * HD];
__device__ __align__(16) __nv_bfloat16 g_wv[HD * HD];
__device__ __align__(16) __nv_bfloat16 g_wo[HD * HD];
__device__ __align__(16) __nv_bfloat16 g_h[2][PN * HD];                // double-buffered h (bf16)
__device__ __align__(16) __nv_bfloat16 g_hfin[PN * HD];                // final h per path
__device__ __align__(16) float         g_c[PN * HD];                   // cell state fp32
__device__ __align__(16) __nv_bfloat16 g_ctx[PN * HD];
__device__ __align__(16) float         g_attn[PN * HD];
__device__ __align__(16) float         g_bias[G4];                     // b_ih + b_hh
__device__ __align__(16) float         g_pooled[HD];
__device__ int g_perm[PN];
__device__ int g_slen[PN];       // sorted lengths (desc)
__device__ int g_activeM[LN];    // #paths with len > t

// ---------------------------------------------------------------------------
// Helpers
// ---------------------------------------------------------------------------
__device__ __forceinline__ uint32_t cvta_s(const void* p) {
    return (uint32_t)__cvta_generic_to_shared(p);
}
__device__ __forceinline__ void cp_cg16(uint32_t d, const void* s) {
    asm volatile("cp.async.cg.shared.global [%0],[%1],16;\n" :: "r"(d), "l"(s));
}
__device__ __forceinline__ void cp_commit() { asm volatile("cp.async.commit_group;\n"); }
__device__ __forceinline__ void cp_wait0()  { asm volatile("cp.async.wait_group 0;\n"); }
__device__ __forceinline__ void cp_wait1()  { asm volatile("cp.async.wait_group 1;\n"); }

__device__ __forceinline__ void mma_bf16(float* c,
                                         uint32_t a0, uint32_t a1, uint32_t a2, uint32_t a3,
                                         uint32_t b0, uint32_t b1) {
    asm volatile(
        "mma.sync.aligned.m16n8k16.row.col.f32.bf16.bf16.f32 "
        "{%0,%1,%2,%3}, {%4,%5,%6,%7}, {%8,%9}, {%0,%1,%2,%3};\n"
        : "+f"(c[0]), "+f"(c[1]), "+f"(c[2]), "+f"(c[3])
        : "r"(a0), "r"(a1), "r"(a2), "r"(a3), "r"(b0), "r"(b1));
}

__device__ __forceinline__ uint32_t packbf2(float lo, float hi) {
    uint32_t r;
    asm("cvt.rn.bf16x2.f32 %0, %1, %2;\n" : "=r"(r) : "f"(hi), "f"(lo));
    return r;
}
__device__ __forceinline__ float bflo(uint32_t u) { return __uint_as_float(u << 16); }
__device__ __forceinline__ float bfhi(uint32_t u) { return __uint_as_float(u & 0xFFFF0000u); }

__device__ __forceinline__ float fast_tanh(float x) {
    float y; asm("tanh.approx.f32 %0,%1;\n" : "=f"(y) : "f"(x)); return y;
}
__device__ __forceinline__ float fsig(float x) { return 0.5f * fast_tanh(0.5f * x) + 0.5f; }

// ---------------------------------------------------------------------------
// Fused prep: block 0 = counting sort (smem scratch only), blocks 1..384 =
// zero g_c/g_h[0], blocks 385..400 = bias sum. Grid 401 x 256.
// ---------------------------------------------------------------------------
__global__ void prep_kernel(const int* __restrict__ lengths,
                            const float* __restrict__ b_ih,
                            const float* __restrict__ b_hh) {
    int b = blockIdx.x, tid = threadIdx.x;
    if (b == 0) {
        __shared__ int s_cnt[LN + 1];
        __shared__ int s_start[LN + 1];
        if (tid <= LN) s_cnt[tid] = 0;
        __syncthreads();
        if (tid < PN) atomicAdd(&s_cnt[lengths[tid]], 1);
        __syncthreads();
        if (tid == 0) {
            int run = 0;
            for (int l = LN; l >= 1; l--) { s_start[l] = run; run += s_cnt[l]; }
            for (int p = 0; p < PN; p++) { int l = lengths[p]; g_perm[s_start[l]++] = p; }
        }
        __syncthreads();
        if (tid < PN) g_slen[tid] = lengths[g_perm[tid]];
        if (tid < LN) {
            int a = 0;
            for (int l = tid + 1; l <= LN; l++) a += s_cnt[l];
            g_activeM[tid] = a;
        }
    } else if (b <= 384) {
        int i = (b - 1) * 256 + tid;
        uint4 z = make_uint4(0u, 0u, 0u, 0u);
        if (i < 65536)      reinterpret_cast<uint4*>(g_c)[i] = z;
        else if (i < 98304) reinterpret_cast<uint4*>(g_h[0])[i - 65536] = z;
    } else {
        int i = (b - 385) * 256 + tid;      // 16 blocks x 256 = 4096
        g_bias[i] = b_ih[i] + b_hh[i];
    }
}

// ---------------------------------------------------------------------------
// All fp32 -> bf16 weight conversions in ONE launch. 4-elem per thread.
// Ranges (in 4-elem units): wih 524288 | whh 1048576 | wv 262144 | wo 262144
// ---------------------------------------------------------------------------
__global__ void cvt_all_kernel(const float* __restrict__ Wih,
                               const float* __restrict__ Whh,
                               const float* __restrict__ Win,
                               const float* __restrict__ Wout) {
    int gid = blockIdx.x * 256 + threadIdx.x;   // 8192 blocks
    const float* src; __nv_bfloat16* dst; int off;
    if (gid < 524288)       { src = Wih;  dst = g_wih; off = gid; }
    else if (gid < 1572864) { src = Whh;  dst = g_whh; off = gid - 524288; }
    else if (gid < 1835008) { src = Win + (size_t)2 * HD * HD; dst = g_wv; off = gid - 1572864; }
    else                    { src = Wout; dst = g_wo;  off = gid - 1835008; }
    int i = off * 4;
    float4 v = *reinterpret_cast<const float4*>(src + i);
    *reinterpret_cast<uint2*>(dst + i) = make_uint2(packbf2(v.x, v.y), packbf2(v.z, v.w));
}

// ---------------------------------------------------------------------------
// Gather + convert: g_x[m = t*256+ps] = bf16(emb[paths[perm[ps]*64 + t]])
// ---------------------------------------------------------------------------
__global__ void gather_kernel(const int* __restrict__ paths, const float* __restrict__ emb) {
    int m = blockIdx.x;
    int t = m >> 8, ps = m & 255;
    if (t >= g_slen[ps]) return;
    int tok = paths[g_perm[ps] * LN + t];
    const float4* src = reinterpret_cast<const float4*>(emb + (size_t)tok * ID);
    int tid = threadIdx.x;   // 64
    float4 v0 = src[tid * 2], v1 = src[tid * 2 + 1];
    uint4 o;
    o.x = packbf2(v0.x, v0.y); o.y = packbf2(v0.z, v0.w);
    o.z = packbf2(v1.x, v1.y); o.w = packbf2(v1.z, v1.w);
    reinterpret_cast<uint4*>(g_x + (size_t)m * ID)[tid] = o;
}

// ---------------------------------------------------------------------------
// bf16 GEMM: C[M,N] = A[M,K] @ B[N,K]^T (+bias). BM=128 BN=64 BK=32, 256 thr.
// 3-stage cp.async pipeline, ONE __syncthreads per k-iter.
// selA: 0=g_x 1=g_hfin 2=g_ctx ; selB: 0=g_wih 1=g_wv 2=g_wo
// selC: 0=g_xproj(bf16) 1=g_ctx(bf16) 2=g_attn(f32)
// skipMode: use g_activeM to skip dead [t][ps] tiles (xproj layout).
// ---------------------------------------------------------------------------
__global__ __launch_bounds__(256)
void gemm_bf16(const float* __restrict__ bias,
               int selA, int selB, int selC, int skipMode,
               int M, int N, int K)
{
    __shared__ uint32_t As[3][128 * 20];   // 30720 B
    __shared__ uint32_t Bs[3][64 * 20];    // 15360 B

    const int tid = threadIdx.x, warp = tid >> 5, lane = tid & 31;
    const int wm = warp >> 1, wn = warp & 1;
    const int m0 = blockIdx.y * 128, n0 = blockIdx.x * 64;

    if (skipMode) {
        int t = m0 >> 8, ps0 = m0 & 255;
        if (g_activeM[t] <= ps0) return;
    }

    const __nv_bfloat16* A = g_x;
    if (selA == 1) A = g_hfin;
    else if (selA == 2) A = g_ctx;
    const __nv_bfloat16* B = g_wih;
    if (selB == 1) B = g_wv;
    else if (selB == 2) B = g_wo;

    float acc[2][4][4];
#pragma unroll
    for (int i = 0; i < 2; i++)
#pragma unroll
        for (int j = 0; j < 4; j++)
#pragma unroll
            for (int q = 0; q < 4; q++) acc[i][j][q] = 0.0f;

    const int nk = K >> 5;
    uint32_t asb[3] = {cvta_s(As[0]), cvta_s(As[1]), cvta_s(As[2])};
    uint32_t bsb[3] = {cvta_s(Bs[0]), cvta_s(Bs[1]), cvta_s(Bs[2])};
    const int lrow = tid >> 2, lc = tid & 3;

    // prologue: stages 0 and 1
#pragma unroll
    for (int s = 0; s < 2; s++) {
        int k0 = s * 32;
        cp_cg16(asb[s] + (lrow * 20 + lc * 4) * 4,        A + (size_t)(m0 + lrow) * K + k0 + lc * 8);
        cp_cg16(asb[s] + ((lrow + 64) * 20 + lc * 4) * 4, A + (size_t)(m0 + lrow + 64) * K + k0 + lc * 8);
        cp_cg16(bsb[s] + (lrow * 20 + lc * 4) * 4,        B + (size_t)(n0 + lrow) * K + k0 + lc * 8);
        cp_commit();
    }

    for (int kt = 0; kt < nk; kt++) {
        if (kt + 1 < nk) cp_wait1(); else cp_wait0();
        __syncthreads();

        if (kt + 2 < nk) {                        // issue stage kt+2
            int s = (kt + 2) % 3, k0 = (kt + 2) * 32;
            cp_cg16(asb[s] + (lrow * 20 + lc * 4) * 4,        A + (size_t)(m0 + lrow) * K + k0 + lc * 8);
            cp_cg16(asb[s] + ((lrow + 64) * 20 + lc * 4) * 4, A + (size_t)(m0 + lrow + 64) * K + k0 + lc * 8);
            cp_cg16(bsb[s] + (lrow * 20 + lc * 4) * 4,        B + (size_t)(n0 + lrow) * K + k0 + lc * 8);
            cp_commit();
        }

        const uint32_t* as = As[kt % 3];
        const uint32_t* bs = Bs[kt % 3];
#pragma unroll
        for (int ks = 0; ks < 2; ks++) {
            int kw = ks * 8 + (lane & 3);
            uint32_t a0[2], a1[2], a2[2], a3[2];
#pragma unroll
            for (int mi = 0; mi < 2; mi++) {
                int r = wm * 32 + mi * 16 + (lane >> 2);
                a0[mi] = as[r * 20 + kw];
                a1[mi] = as[(r + 8) * 20 + kw];
                a2[mi] = as[r * 20 + kw + 4];
                a3[mi] = as[(r + 8) * 20 + kw + 4];
            }
#pragma unroll
            for (int nj = 0; nj < 4; nj++) {
                int cn = wn * 32 + nj * 8 + (lane >> 2);
                uint32_t b0 = bs[cn * 20 + kw], b1 = bs[cn * 20 + kw + 4];
                mma_bf16(acc[0][nj], a0[0], a1[0], a2[0], a3[0], b0, b1);
                mma_bf16(acc[1][nj], a0[1], a1[1], a2[1], a3[1], b0, b1);
            }
        }
    }

#pragma unroll
    for (int mi = 0; mi < 2; mi++) {
#pragma unroll
        for (int half = 0; half < 2; half++) {
            int row = m0 + wm * 32 + mi * 16 + (lane >> 2) + half * 8;
#pragma unroll
            for (int nj = 0; nj < 4; nj++) {
                int col = n0 + wn * 32 + nj * 8 + 2 * (lane & 3);
                float v0 = acc[mi][nj][half * 2];
                float v1 = acc[mi][nj][half * 2 + 1];
                if (bias) { v0 += bias[col]; v1 += bias[col + 1]; }
                if (selC == 2) {
                    g_attn[(size_t)row * N + col]     = v0;
                    g_attn[(size_t)row * N + col + 1] = v1;
                } else {
                    __nv_bfloat16* C = (selC == 0) ? g_xproj : g_ctx;
                    *reinterpret_cast<uint32_t*>(C + (size_t)row * N + col) = packbf2(v0, v1);
                }
            }
        }
    }
}

// ---------------------------------------------------------------------------
// One LSTM time step. Grid (32 jtiles, 4 ptiles) x 256 threads.
// Block: 64 p-rows x 32 j-cols x 4 gates (N=128 gate-cols), K=1024.
// 3-stage cp.async pipeline, one sync per k-iter. c fp32 in global,
// h bf16 double-buffered. No inter-block sync within a step.
// SMEM: H stages 3x1280 w + W stages 3x2560 w = 11520 w (46 KB);
// epilogue reuses the same array as 64x132 f32 gate tile.
// ---------------------------------------------------------------------------
__global__ __launch_bounds__(256)
void lstm_step_kernel(int t)
{
    __shared__ uint32_t SM[11520];
    const int activeM = g_activeM[t];
    const int pbase = blockIdx.y * 64;
    if (pbase >= activeM) return;
    const int jb = blockIdx.x;                    // j-tile [jb*32, +32)
    const int tid = threadIdx.x, warp = tid >> 5, lane = tid & 31;
    const int wm = warp >> 2, wn = warp & 3;      // 2 x 4 warps, warp tile 32x32
    const __nv_bfloat16* hin = g_h[t & 1];

    uint32_t hsb[3] = {cvta_s(SM), cvta_s(SM + 1280), cvta_s(SM + 2560)};
    uint32_t wsb[3] = {cvta_s(SM + 3840), cvta_s(SM + 6400), cvta_s(SM + 8960)};

    float acc[2][4][4];
#pragma unroll
    for (int i = 0; i < 2; i++)
#pragma unroll
        for (int j = 0; j < 4; j++)
#pragma unroll
            for (int q = 0; q < 4; q++) acc[i][j][q] = 0.0f;

    const int arow = tid >> 2, ach = tid & 3;     // H tile: 64 rows x 4 x 16B

    // prologue: stages 0 and 1
#pragma unroll
    for (int s = 0; s < 2; s++) {
        int k0 = s * 32;
        cp_cg16(hsb[s] + (arow * 20 + ach * 4) * 4, hin + (size_t)(pbase + arow) * HD + k0 + ach * 8);
#pragma unroll
        for (int i = 0; i < 2; i++) {
            int e = tid + i * 256, c = e >> 2, ch = e & 3;
            int wr = (c >> 5) * HD + jb * 32 + (c & 31);
            cp_cg16(wsb[s] + (c * 20 + ch * 4) * 4, g_whh + (size_t)wr * HD + k0 + ch * 8);
        }
        cp_commit();
    }

    for (int kt = 0; kt < 32; kt++) {
        if (kt + 1 < 32) cp_wait1(); else cp_wait0();
        __syncthreads();

        if (kt + 2 < 32) {
            int s = (kt + 2) % 3, k0 = (kt + 2) * 32;
            cp_cg16(hsb[s] + (arow * 20 + ach * 4) * 4,
                    hin + (size_t)(pbase + arow) * HD + k0 + ach * 8);
#pragma unroll
            for (int i = 0; i < 2; i++) {
                int e = tid + i * 256, c = e >> 2, ch = e & 3;
                int wr = (c >> 5) * HD + jb * 32 + (c & 31);
                cp_cg16(wsb[s] + (c * 20 + ch * 4) * 4, g_whh + (size_t)wr * HD + k0 + ch * 8);
            }
            cp_commit();
        }

        const uint32_t* as = SM + (kt % 3) * 1280;
        const uint32_t* bs = SM + 3840 + (kt % 3) * 2560;
#pragma unroll
        for (int ks = 0; ks < 2; ks++) {
            int kw = ks * 8 + (lane & 3);
            uint32_t a0[2], a1[2], a2[2], a3[2];
#pragma unroll
            for (int mi = 0; mi < 2; mi++) {
                int r = wm * 32 + mi * 16 + (lane >> 2);
                a0[mi] = as[r * 20 + kw];
                a1[mi] = as[(r + 8) * 20 + kw];
                a2[mi] = as[r * 20 + kw + 4];
                a3[mi] = as[(r + 8) * 20 + kw + 4];
            }
#pragma unroll
            for (int nj = 0; nj < 4; nj++) {
                int cn = wn * 32 + nj * 8 + (lane >> 2);
                uint32_t b0 = bs[cn * 20 + kw], b1 = bs[cn * 20 + kw + 4];
                mma_bf16(acc[0][nj], a0[0], a1[0], a2[0], a3[0], b0, b1);
                mma_bf16(acc[1][nj], a0[1], a1[1], a2[1], a3[1], b0, b1);
            }
        }
        __syncthreads();   // protect buffer (kt%3) before it is re-filled at kt+3
    }

    // gates tile to smem (reuse SM as 64 x 132 floats)
    float* gsm = (float*)SM;
    __syncthreads();
#pragma unroll
    for (int mi = 0; mi < 2; mi++)
#pragma unroll
        for (int half = 0; half < 2; half++) {
            int row = wm * 32 + mi * 16 + (lane >> 2) + half * 8;
#pragma unroll
            for (int nj = 0; nj < 4; nj++) {
                int col = wn * 32 + nj * 8 + 2 * (lane & 3);
                gsm[row * 132 + col]     = acc[mi][nj][half * 2];
                gsm[row * 132 + col + 1] = acc[mi][nj][half * 2 + 1];
            }
        }
    __syncthreads();

    // pointwise: thread -> p-row (tid>>2), 8 j's ((tid&3)*8)
    const int pl = tid >> 2;
    const int p  = pbase + pl;
    const int len = g_slen[p];
    if (t < len) {
        const int jloc = (tid & 3) * 8;
        const int jg = jb * 32 + jloc;
        const __nv_bfloat16* xrow = g_xproj + (size_t)t * PN * G4 + (size_t)p * G4;
        float gate[4][8];
#pragma unroll
        for (int g = 0; g < 4; g++) {
            uint4 xv = *reinterpret_cast<const uint4*>(xrow + g * HD + jg);
            float xb[8] = { bflo(xv.x), bfhi(xv.x), bflo(xv.y), bfhi(xv.y),
                            bflo(xv.z), bfhi(xv.z), bflo(xv.w), bfhi(xv.w) };
            float4 bv0 = *reinterpret_cast<const float4*>(g_bias + g * HD + jg);
            float4 bv1 = *reinterpret_cast<const float4*>(g_bias + g * HD + jg + 4);
            float bb[8] = { bv0.x, bv0.y, bv0.z, bv0.w, bv1.x, bv1.y, bv1.z, bv1.w };
#pragma unroll
            for (int e = 0; e < 8; e++)
                gate[g][e] = gsm[pl * 132 + g * 32 + jloc + e] + xb[e] + bb[e];
        }
        float4 c0 = *reinterpret_cast<const float4*>(g_c + (size_t)p * HD + jg);
        float4 c1 = *reinterpret_cast<const float4*>(g_c + (size_t)p * HD + jg + 4);
        float cc[8] = { c0.x, c0.y, c0.z, c0.w, c1.x, c1.y, c1.z, c1.w };
        float hh[8];
#pragma unroll
        for (int e = 0; e < 8; e++) {
            float cn = fsig(gate[1][e]) * cc[e] + fsig(gate[0][e]) * fast_tanh(gate[2][e]);
            cc[e] = cn;
            hh[e] = fsig(gate[3][e]) * fast_tanh(cn);
        }
        *reinterpret_cast<float4*>(g_c + (size_t)p * HD + jg)     = make_float4(cc[0], cc[1], cc[2], cc[3]);
        *reinterpret_cast<float4*>(g_c + (size_t)p * HD + jg + 4) = make_float4(cc[4], cc[5], cc[6], cc[7]);
        uint4 hp;
        hp.x = packbf2(hh[0], hh[1]); hp.y = packbf2(hh[2], hh[3]);
        hp.z = packbf2(hh[4], hh[5]); hp.w = packbf2(hh[6], hh[7]);
        *reinterpret_cast<uint4*>(g_h[(t + 1) & 1] + (size_t)p * HD + jg) = hp;
    }
}

// ---------------------------------------------------------------------------
// Collect final h per path from the parity buffer g_h[len & 1]
// ---------------------------------------------------------------------------
__global__ void collect_kernel() {
    int p = blockIdx.x;                        // 256 blocks x 128 threads
    int parity = g_slen[p] & 1;
    const uint4* src = reinterpret_cast<const uint4*>(g_h[parity] + (size_t)p * HD);
    uint4* dst = reinterpret_cast<uint4*>(g_hfin + (size_t)p * HD);
    dst[threadIdx.x] = src[threadIdx.x];
}

// ---------------------------------------------------------------------------
// Maxpool over paths (permutation-invariant)
// ---------------------------------------------------------------------------
__global__ void pool_kernel() {
    int j = blockIdx.x * blockDim.x + threadIdx.x;   // 8 x 128
    float m = -3.402823466e+38f;
#pragma unroll 4
    for (int p = 0; p < PN; p++) m = fmaxf(m, g_attn[p * HD + j]);
    g_pooled[j] = m;
}

// ---------------------------------------------------------------------------
// Final linear + sigmoid
// ---------------------------------------------------------------------------
__global__ void final_kernel(const float* __restrict__ Wlin,
                             const float* __restrict__ blin,
                             float* __restrict__ out)
{
    __shared__ float red0[8], red1[8];
    int tid = threadIdx.x;                      // 256
    float s0 = 0.0f, s1 = 0.0f;
    for (int j = tid; j < HD; j += 256) {
        float pv = g_pooled[j];
        s0 += pv * Wlin[j];
        s1 += pv * Wlin[HD + j];
    }
#pragma unroll
    for (int o = 16; o; o >>= 1) {
        s0 += __shfl_xor_sync(0xFFFFFFFFu, s0, o);
        s1 += __shfl_xor_sync(0xFFFFFFFFu, s1, o);
    }
    if ((tid & 31) == 0) { red0[tid >> 5] = s0; red1[tid >> 5] = s1; }
    __syncthreads();
    if (tid == 0) {
        float z0 = blin[0], z1 = blin[1];
#pragma unroll
        for (int w = 0; w < 8; w++) { z0 += red0[w]; z1 += red1[w]; }
        out[0] = 1.0f / (1.0f + expf(-z0));
        out[1] = 1.0f / (1.0f + expf(-z1));
    }
}

// ---------------------------------------------------------------------------
// Launch. Order chosen so launch index 5 (ncu -s 5 -c 1) = lstm_step t=1.
// ---------------------------------------------------------------------------
extern "C" void kernel_launch(void* const* d_in, const int* in_sizes, int n_in,
                              void* d_out, int out_size)
{
    (void)in_sizes; (void)n_in; (void)out_size;
    const int*   paths   = (const int*)  d_in[0];
    const int*   lengths = (const int*)  d_in[1];
    const float* emb     = (const float*)d_in[2];
    const float* W_ih    = (const float*)d_in[3];
    const float* W_hh    = (const float*)d_in[4];
    const float* b_ih    = (const float*)d_in[5];
    const float* b_hh    = (const float*)d_in[6];
    const float* W_in    = (const float*)d_in[7];
    const float* b_in    = (const float*)d_in[8];
    const float* W_out   = (const float*)d_in[9];
    const float* b_out   = (const float*)d_in[10];
    const float* W_lin   = (const float*)d_in[11];
    const float* b_lin   = (const float*)d_in[12];
    float* out = (float*)d_out;

    // 0: sort + zero + bias
    prep_kernel<<<401, 256>>>(lengths, b_ih, b_hh);
    // 1: all weight conversions
    cvt_all_kernel<<<8192, 256>>>(W_ih, W_hh, W_in, W_out);
    // 2: gather embeddings (sorted path order)
    gather_kernel<<<LN * PN, 64>>>(paths, emb);
    // 3: xproj = gathered_x @ W_ih^T -> bf16 [t][ps][4H], dead tiles skipped
    gemm_bf16<<<dim3(G4 / 64, (PN * LN) / 128), 256>>>(
        nullptr, /*selA*/0, /*selB*/0, /*selC*/0, /*skip*/1, PN * LN, G4, ID);

    // 4..67: recurrence steps (launch index 5 == t=1, the ncu target)
    for (int t = 0; t < LN; t++)
        lstm_step_kernel<<<dim3(32, 4), 256>>>(t);

    collect_kernel<<<PN, 128>>>();

    // attention collapses (softmax over length-1 axis == 1):
    gemm_bf16<<<dim3(HD / 64, PN / 128), 256>>>(
        b_in + 2 * HD, /*selA*/1, /*selB*/1, /*selC*/1, /*skip*/0, PN, HD, HD);
    gemm_bf16<<<dim3(HD / 64, PN / 128), 256>>>(
        b_out, /*selA*/2, /*selB*/2, /*selC*/2, /*skip*/0, PN, HD, HD);

    pool_kernel<<<8, 128>>>();
    final_kernel<<<1, 256>>>(W_lin, b_lin, out);
}

// round 9
// speedup vs baseline: 4.3134x; 1.1458x over previous
#include <cuda_runtime.h>
#include <cuda_bf16.h>
#include <cstdint>

// Problem constants
#define PN   256      // num paths
#define LN   64       // max path length
#define ID   512      // input dim
#define HD   1024     // hidden dim
#define G4   4096     // 4*H

// ---------------------------------------------------------------------------
// Scratch (device globals; allocation-free). NEVER passed from host code.
// ---------------------------------------------------------------------------
__device__ __align__(16) __nv_bfloat16 g_x[(size_t)LN * PN * ID];      // gathered emb (sorted p)
__device__ __align__(16) __nv_bfloat16 g_xproj[(size_t)LN * PN * G4];  // [t][ps][4H]
__device__ __align__(16) __nv_bfloat16 g_wih[G4 * ID];
__device__ __align__(16) __nv_bfloat16 g_whh[G4 * HD];
__device__ __align__(16) __nv_bfloat16 g_wv[HD * HD];
__device__ __align__(16) __nv_bfloat16 g_wo[HD * HD];
__device__ __align__(16) __nv_bfloat16 g_h[2][PN * HD];                // double-buffered h (bf16)
__device__ __align__(16) __nv_bfloat16 g_hfin[PN * HD];                // final h per path
__device__ __align__(16) float         g_c[PN * HD];                   // cell state fp32
__device__ __align__(16) __nv_bfloat16 g_ctx[PN * HD];
__device__ __align__(16) float         g_attn[PN * HD];
__device__ __align__(16) float         g_bias[G4];                     // b_ih + b_hh
__device__ __align__(16) float         g_pooled[HD];
__device__ int g_perm[PN];
__device__ int g_slen[PN];       // sorted lengths (desc)
__device__ int g_activeM[LN];    // #paths with len > t

// ---------------------------------------------------------------------------
// Helpers
// ---------------------------------------------------------------------------
__device__ __forceinline__ uint32_t cvta_s(const void* p) {
    return (uint32_t)__cvta_generic_to_shared(p);
}
__device__ __forceinline__ void cp_cg16(uint32_t d, const void* s) {
    asm volatile("cp.async.cg.shared.global [%0],[%1],16;\n" :: "r"(d), "l"(s));
}
__device__ __forceinline__ void cp_commit() { asm volatile("cp.async.commit_group;\n"); }
__device__ __forceinline__ void cp_wait0()  { asm volatile("cp.async.wait_group 0;\n"); }
__device__ __forceinline__ void cp_wait1()  { asm volatile("cp.async.wait_group 1;\n"); }

__device__ __forceinline__ void ldsm_x4(uint32_t& r0, uint32_t& r1, uint32_t& r2, uint32_t& r3,
                                        uint32_t addr) {
    asm volatile("ldmatrix.sync.aligned.m8n8.x4.shared.b16 {%0,%1,%2,%3}, [%4];\n"
                 : "=r"(r0), "=r"(r1), "=r"(r2), "=r"(r3) : "r"(addr));
}

__device__ __forceinline__ void mma_bf16(float* c,
                                         uint32_t a0, uint32_t a1, uint32_t a2, uint32_t a3,
                                         uint32_t b0, uint32_t b1) {
    asm volatile(
        "mma.sync.aligned.m16n8k16.row.col.f32.bf16.bf16.f32 "
        "{%0,%1,%2,%3}, {%4,%5,%6,%7}, {%8,%9}, {%0,%1,%2,%3};\n"
        : "+f"(c[0]), "+f"(c[1]), "+f"(c[2]), "+f"(c[3])
        : "r"(a0), "r"(a1), "r"(a2), "r"(a3), "r"(b0), "r"(b1));
}

__device__ __forceinline__ uint32_t packbf2(float lo, float hi) {
    uint32_t r;
    asm("cvt.rn.bf16x2.f32 %0, %1, %2;\n" : "=r"(r) : "f"(hi), "f"(lo));
    return r;
}
__device__ __forceinline__ float bflo(uint32_t u) { return __uint_as_float(u << 16); }
__device__ __forceinline__ float bfhi(uint32_t u) { return __uint_as_float(u & 0xFFFF0000u); }

__device__ __forceinline__ float fast_tanh(float x) {
    float y; asm("tanh.approx.f32 %0,%1;\n" : "=f"(y) : "f"(x)); return y;
}
__device__ __forceinline__ float fsig(float x) { return 0.5f * fast_tanh(0.5f * x) + 0.5f; }

// Per-lane ldmatrix address offsets (bytes) for 20-word (80B) padded rows.
// A (.x4 -> a0..a3 of one m16 block): rows lane&15, k half by lane>>4.
__device__ __forceinline__ int ldsm_a_off(int lane) {
    return ((lane & 15) * 20 + (lane >> 4) * 4) * 4;
}
// B (.x4 -> b0,b1 of n-octet pair): rows lane&7 (+8 rows if lane>=16), k half by bit3.
__device__ __forceinline__ int ldsm_b_off(int lane) {
    return ((lane & 7) * 20 + ((lane >> 3) & 1) * 4 + ((lane >> 4) & 1) * 160) * 4;
}

// ---------------------------------------------------------------------------
// Fused prep: block 0 = counting sort (smem scratch only), blocks 1..384 =
// zero g_c/g_h[0], blocks 385..400 = bias sum. Grid 401 x 256.
// ---------------------------------------------------------------------------
__global__ void prep_kernel(const int* __restrict__ lengths,
                            const float* __restrict__ b_ih,
                            const float* __restrict__ b_hh) {
    int b = blockIdx.x, tid = threadIdx.x;
    if (b == 0) {
        __shared__ int s_cnt[LN + 1];
        __shared__ int s_start[LN + 1];
        if (tid <= LN) s_cnt[tid] = 0;
        __syncthreads();
        if (tid < PN) atomicAdd(&s_cnt[lengths[tid]], 1);
        __syncthreads();
        if (tid == 0) {
            int run = 0;
            for (int l = LN; l >= 1; l--) { s_start[l] = run; run += s_cnt[l]; }
            for (int p = 0; p < PN; p++) { int l = lengths[p]; g_perm[s_start[l]++] = p; }
        }
        __syncthreads();
        if (tid < PN) g_slen[tid] = lengths[g_perm[tid]];
        if (tid < LN) {
            int a = 0;
            for (int l = tid + 1; l <= LN; l++) a += s_cnt[l];
            g_activeM[tid] = a;
        }
    } else if (b <= 384) {
        int i = (b - 1) * 256 + tid;
        uint4 z = make_uint4(0u, 0u, 0u, 0u);
        if (i < 65536)      reinterpret_cast<uint4*>(g_c)[i] = z;
        else if (i < 98304) reinterpret_cast<uint4*>(g_h[0])[i - 65536] = z;
    } else {
        int i = (b - 385) * 256 + tid;      // 16 blocks x 256 = 4096
        g_bias[i] = b_ih[i] + b_hh[i];
    }
}

// ---------------------------------------------------------------------------
// All fp32 -> bf16 weight conversions in ONE launch. 4-elem per thread.
// ---------------------------------------------------------------------------
__global__ void cvt_all_kernel(const float* __restrict__ Wih,
                               const float* __restrict__ Whh,
                               const float* __restrict__ Win,
                               const float* __restrict__ Wout) {
    int gid = blockIdx.x * 256 + threadIdx.x;   // 8192 blocks
    const float* src; __nv_bfloat16* dst; int off;
    if (gid < 524288)       { src = Wih;  dst = g_wih; off = gid; }
    else if (gid < 1572864) { src = Whh;  dst = g_whh; off = gid - 524288; }
    else if (gid < 1835008) { src = Win + (size_t)2 * HD * HD; dst = g_wv; off = gid - 1572864; }
    else                    { src = Wout; dst = g_wo;  off = gid - 1835008; }
    int i = off * 4;
    float4 v = *reinterpret_cast<const float4*>(src + i);
    *reinterpret_cast<uint2*>(dst + i) = make_uint2(packbf2(v.x, v.y), packbf2(v.z, v.w));
}

// ---------------------------------------------------------------------------
// Gather + convert: g_x[m = t*256+ps] = bf16(emb[paths[perm[ps]*64 + t]])
// ---------------------------------------------------------------------------
__global__ void gather_kernel(const int* __restrict__ paths, const float* __restrict__ emb) {
    int m = blockIdx.x;
    int t = m >> 8, ps = m & 255;
    if (t >= g_slen[ps]) return;
    int tok = paths[g_perm[ps] * LN + t];
    const float4* src = reinterpret_cast<const float4*>(emb + (size_t)tok * ID);
    int tid = threadIdx.x;   // 64
    float4 v0 = src[tid * 2], v1 = src[tid * 2 + 1];
    uint4 o;
    o.x = packbf2(v0.x, v0.y); o.y = packbf2(v0.z, v0.w);
    o.z = packbf2(v1.x, v1.y); o.w = packbf2(v1.z, v1.w);
    reinterpret_cast<uint4*>(g_x + (size_t)m * ID)[tid] = o;
}

// ---------------------------------------------------------------------------
// bf16 GEMM: C[M,N] = A[M,K] @ B[N,K]^T (+bias). BM=128 BN=64 BK=32, 256 thr.
// 3-stage cp.async pipeline + ldmatrix fragment loads.
// selA: 0=g_x 1=g_hfin 2=g_ctx ; selB: 0=g_wih 1=g_wv 2=g_wo
// selC: 0=g_xproj(bf16) 1=g_ctx(bf16) 2=g_attn(f32)
// ---------------------------------------------------------------------------
#define GA_STAGE 10240     // bytes per A stage (128 rows x 80 B)
#define GB_STAGE 5120      // bytes per B stage (64 rows x 80 B)

__global__ __launch_bounds__(256)
void gemm_bf16(const float* __restrict__ bias,
               int selA, int selB, int selC, int skipMode,
               int M, int N, int K)
{
    __shared__ uint32_t As[3][128 * 20];   // 30720 B
    __shared__ uint32_t Bs[3][64 * 20];    // 15360 B

    const int tid = threadIdx.x, warp = tid >> 5, lane = tid & 31;
    const int wm = warp >> 1, wn = warp & 1;
    const int m0 = blockIdx.y * 128, n0 = blockIdx.x * 64;

    if (skipMode) {
        int t = m0 >> 8, ps0 = m0 & 255;
        if (g_activeM[t] <= ps0) return;
    }

    const __nv_bfloat16* A = g_x;
    if (selA == 1) A = g_hfin;
    else if (selA == 2) A = g_ctx;
    const __nv_bfloat16* B = g_wih;
    if (selB == 1) B = g_wv;
    else if (selB == 2) B = g_wo;

    float acc[2][4][4];
#pragma unroll
    for (int i = 0; i < 2; i++)
#pragma unroll
        for (int j = 0; j < 4; j++)
#pragma unroll
            for (int q = 0; q < 4; q++) acc[i][j][q] = 0.0f;

    const int nk = K >> 5;
    const uint32_t a_base = cvta_s(As);
    const uint32_t b_base = cvta_s(Bs);
    const int lrow = tid >> 2, lc = tid & 3;
    const int aoff = ldsm_a_off(lane), boff = ldsm_b_off(lane);

    // prologue: stages 0 and 1
#pragma unroll
    for (int s = 0; s < 2; s++) {
        int k0 = s * 32;
        uint32_t ab = a_base + s * GA_STAGE, bb_ = b_base + s * GB_STAGE;
        cp_cg16(ab + (lrow * 20 + lc * 4) * 4,        A + (size_t)(m0 + lrow) * K + k0 + lc * 8);
        cp_cg16(ab + ((lrow + 64) * 20 + lc * 4) * 4, A + (size_t)(m0 + lrow + 64) * K + k0 + lc * 8);
        cp_cg16(bb_ + (lrow * 20 + lc * 4) * 4,       B + (size_t)(n0 + lrow) * K + k0 + lc * 8);
        cp_commit();
    }

    for (int kt = 0; kt < nk; kt++) {
        if (kt + 1 < nk) cp_wait1(); else cp_wait0();
        __syncthreads();

        if (kt + 2 < nk) {                        // issue stage kt+2
            int s = (kt + 2) % 3, k0 = (kt + 2) * 32;
            uint32_t ab = a_base + s * GA_STAGE, bb_ = b_base + s * GB_STAGE;
            cp_cg16(ab + (lrow * 20 + lc * 4) * 4,        A + (size_t)(m0 + lrow) * K + k0 + lc * 8);
            cp_cg16(ab + ((lrow + 64) * 20 + lc * 4) * 4, A + (size_t)(m0 + lrow + 64) * K + k0 + lc * 8);
            cp_cg16(bb_ + (lrow * 20 + lc * 4) * 4,       B + (size_t)(n0 + lrow) * K + k0 + lc * 8);
            cp_commit();
        }

        const uint32_t asc = a_base + (kt % 3) * GA_STAGE;
        const uint32_t bsc = b_base + (kt % 3) * GB_STAGE;
#pragma unroll
        for (int ks = 0; ks < 2; ks++) {
            const int kby = ks * 32;      // ks*8 words * 4 B
            uint32_t a0[2], a1[2], a2[2], a3[2];
#pragma unroll
            for (int mi = 0; mi < 2; mi++)
                ldsm_x4(a0[mi], a1[mi], a2[mi], a3[mi],
                        asc + (wm * 32 + mi * 16) * 80 + kby + aoff);
            uint32_t bb[8];
#pragma unroll
            for (int njp = 0; njp < 2; njp++)
                ldsm_x4(bb[njp * 4], bb[njp * 4 + 1], bb[njp * 4 + 2], bb[njp * 4 + 3],
                        bsc + (wn * 32 + njp * 16) * 80 + kby + boff);
#pragma unroll
            for (int nj = 0; nj < 4; nj++) {
                uint32_t b0 = bb[(nj >> 1) * 4 + (nj & 1) * 2];
                uint32_t b1 = bb[(nj >> 1) * 4 + (nj & 1) * 2 + 1];
                mma_bf16(acc[0][nj], a0[0], a1[0], a2[0], a3[0], b0, b1);
                mma_bf16(acc[1][nj], a0[1], a1[1], a2[1], a3[1], b0, b1);
            }
        }
    }

#pragma unroll
    for (int mi = 0; mi < 2; mi++) {
#pragma unroll
        for (int half = 0; half < 2; half++) {
            int row = m0 + wm * 32 + mi * 16 + (lane >> 2) + half * 8;
#pragma unroll
            for (int nj = 0; nj < 4; nj++) {
                int col = n0 + wn * 32 + nj * 8 + 2 * (lane & 3);
                float v0 = acc[mi][nj][half * 2];
                float v1 = acc[mi][nj][half * 2 + 1];
                if (bias) { v0 += bias[col]; v1 += bias[col + 1]; }
                if (selC == 2) {
                    g_attn[(size_t)row * N + col]     = v0;
                    g_attn[(size_t)row * N + col + 1] = v1;
                } else {
                    __nv_bfloat16* C = (selC == 0) ? g_xproj : g_ctx;
                    *reinterpret_cast<uint32_t*>(C + (size_t)row * N + col) = packbf2(v0, v1);
                }
            }
        }
    }
}

// ---------------------------------------------------------------------------
// One LSTM time step. Grid (32 jtiles, 4 ptiles) x 256 threads.
// Block: 64 p-rows x 32 j-cols x 4 gates (N=128 gate-cols), K=1024.
// 3-stage cp.async pipeline + ldmatrix fragment loads.
// SMEM: H stages 3x1280 w + W stages 3x2560 w = 11520 w (46 KB);
// epilogue reuses the array as 64x132 f32 gate tile.
// ---------------------------------------------------------------------------
#define LH_STAGE 5120      // bytes per H stage (64 rows x 80 B)
#define LW_STAGE 10240     // bytes per W stage (128 rows x 80 B)

__global__ __launch_bounds__(256)
void lstm_step_kernel(int t)
{
    __shared__ uint32_t SM[11520];
    const int activeM = g_activeM[t];
    const int pbase = blockIdx.y * 64;
    if (pbase >= activeM) return;
    const int jb = blockIdx.x;                    // j-tile [jb*32, +32)
    const int tid = threadIdx.x, warp = tid >> 5, lane = tid & 31;
    const int wm = warp >> 2, wn = warp & 3;      // 2 x 4 warps, warp tile 32x32
    const __nv_bfloat16* hin = g_h[t & 1];

    const uint32_t h_base = cvta_s(SM);
    const uint32_t w_base = h_base + 3 * LH_STAGE;

    float acc[2][4][4];
#pragma unroll
    for (int i = 0; i < 2; i++)
#pragma unroll
        for (int j = 0; j < 4; j++)
#pragma unroll
            for (int q = 0; q < 4; q++) acc[i][j][q] = 0.0f;

    const int arow = tid >> 2, ach = tid & 3;     // H tile: 64 rows x 4 x 16B
    const int aoff = ldsm_a_off(lane), boff = ldsm_b_off(lane);

    // prologue: stages 0 and 1
#pragma unroll
    for (int s = 0; s < 2; s++) {
        int k0 = s * 32;
        cp_cg16(h_base + s * LH_STAGE + (arow * 20 + ach * 4) * 4,
                hin + (size_t)(pbase + arow) * HD + k0 + ach * 8);
#pragma unroll
        for (int i = 0; i < 2; i++) {
            int e = tid + i * 256, c = e >> 2, ch = e & 3;
            int wr = (c >> 5) * HD + jb * 32 + (c & 31);
            cp_cg16(w_base + s * LW_STAGE + (c * 20 + ch * 4) * 4,
                    g_whh + (size_t)wr * HD + k0 + ch * 8);
        }
        cp_commit();
    }

    for (int kt = 0; kt < 32; kt++) {
        if (kt + 1 < 32) cp_wait1(); else cp_wait0();
        __syncthreads();

        if (kt + 2 < 32) {
            int s = (kt + 2) % 3, k0 = (kt + 2) * 32;
            cp_cg16(h_base + s * LH_STAGE + (arow * 20 + ach * 4) * 4,
                    hin + (size_t)(pbase + arow) * HD + k0 + ach * 8);
#pragma unroll
            for (int i = 0; i < 2; i++) {
                int e = tid + i * 256, c = e >> 2, ch = e & 3;
                int wr = (c >> 5) * HD + jb * 32 + (c & 31);
                cp_cg16(w_base + s * LW_STAGE + (c * 20 + ch * 4) * 4,
                        g_whh + (size_t)wr * HD + k0 + ch * 8);
            }
            cp_commit();
        }

        const uint32_t asc = h_base + (kt % 3) * LH_STAGE;
        const uint32_t bsc = w_base + (kt % 3) * LW_STAGE;
#pragma unroll
        for (int ks = 0; ks < 2; ks++) {
            const int kby = ks * 32;
            uint32_t a0[2], a1[2], a2[2], a3[2];
#pragma unroll
            for (int mi = 0; mi < 2; mi++)
                ldsm_x4(a0[mi], a1[mi], a2[mi], a3[mi],
                        asc + (wm * 32 + mi * 16) * 80 + kby + aoff);
            uint32_t bb[8];
#pragma unroll
            for (int njp = 0; njp < 2; njp++)
                ldsm_x4(bb[njp * 4], bb[njp * 4 + 1], bb[njp * 4 + 2], bb[njp * 4 + 3],
                        bsc + (wn * 32 + njp * 16) * 80 + kby + boff);
#pragma unroll
            for (int nj = 0; nj < 4; nj++) {
                uint32_t b0 = bb[(nj >> 1) * 4 + (nj & 1) * 2];
                uint32_t b1 = bb[(nj >> 1) * 4 + (nj & 1) * 2 + 1];
                mma_bf16(acc[0][nj], a0[0], a1[0], a2[0], a3[0], b0, b1);
                mma_bf16(acc[1][nj], a0[1], a1[1], a2[1], a3[1], b0, b1);
            }
        }
        __syncthreads();   // protect buffer (kt%3) before refill at kt+3
    }

    // gates tile to smem (reuse SM as 64 x 132 floats)
    float* gsm = (float*)SM;
#pragma unroll
    for (int mi = 0; mi < 2; mi++)
#pragma unroll
        for (int half = 0; half < 2; half++) {
            int row = wm * 32 + mi * 16 + (lane >> 2) + half * 8;
#pragma unroll
            for (int nj = 0; nj < 4; nj++) {
                int col = wn * 32 + nj * 8 + 2 * (lane & 3);
                gsm[row * 132 + col]     = acc[mi][nj][half * 2];
                gsm[row * 132 + col + 1] = acc[mi][nj][half * 2 + 1];
            }
        }
    __syncthreads();

    // pointwise: thread -> p-row (tid>>2), 8 j's ((tid&3)*8)
    const int pl = tid >> 2;
    const int p  = pbase + pl;
    const int len = g_slen[p];
    if (t < len) {
        const int jloc = (tid & 3) * 8;
        const int jg = jb * 32 + jloc;
        const __nv_bfloat16* xrow = g_xproj + (size_t)t * PN * G4 + (size_t)p * G4;
        float gate[4][8];
#pragma unroll
        for (int g = 0; g < 4; g++) {
            uint4 xv = *reinterpret_cast<const uint4*>(xrow + g * HD + jg);
            float xb[8] = { bflo(xv.x), bfhi(xv.x), bflo(xv.y), bfhi(xv.y),
                            bflo(xv.z), bfhi(xv.z), bflo(xv.w), bfhi(xv.w) };
            float4 bv0 = *reinterpret_cast<const float4*>(g_bias + g * HD + jg);
            float4 bv1 = *reinterpret_cast<const float4*>(g_bias + g * HD + jg + 4);
            float bb[8] = { bv0.x, bv0.y, bv0.z, bv0.w, bv1.x, bv1.y, bv1.z, bv1.w };
#pragma unroll
            for (int e = 0; e < 8; e++)
                gate[g][e] = gsm[pl * 132 + g * 32 + jloc + e] + xb[e] + bb[e];
        }
        float4 c0 = *reinterpret_cast<const float4*>(g_c + (size_t)p * HD + jg);
        float4 c1 = *reinterpret_cast<const float4*>(g_c + (size_t)p * HD + jg + 4);
        float cc[8] = { c0.x, c0.y, c0.z, c0.w, c1.x, c1.y, c1.z, c1.w };
        float hh[8];
#pragma unroll
        for (int e = 0; e < 8; e++) {
            float cn = fsig(gate[1][e]) * cc[e] + fsig(gate[0][e]) * fast_tanh(gate[2][e]);
            cc[e] = cn;
            hh[e] = fsig(gate[3][e]) * fast_tanh(cn);
        }
        *reinterpret_cast<float4*>(g_c + (size_t)p * HD + jg)     = make_float4(cc[0], cc[1], cc[2], cc[3]);
        *reinterpret_cast<float4*>(g_c + (size_t)p * HD + jg + 4) = make_float4(cc[4], cc[5], cc[6], cc[7]);
        uint4 hp;
        hp.x = packbf2(hh[0], hh[1]); hp.y = packbf2(hh[2], hh[3]);
        hp.z = packbf2(hh[4], hh[5]); hp.w = packbf2(hh[6], hh[7]);
        *reinterpret_cast<uint4*>(g_h[(t + 1) & 1] + (size_t)p * HD + jg) = hp;
    }
}

// ---------------------------------------------------------------------------
// Collect final h per path from the parity buffer g_h[len & 1]
// ---------------------------------------------------------------------------
__global__ void collect_kernel() {
    int p = blockIdx.x;                        // 256 blocks x 128 threads
    int parity = g_slen[p] & 1;
    const uint4* src = reinterpret_cast<const uint4*>(g_h[parity] + (size_t)p * HD);
    uint4* dst = reinterpret_cast<uint4*>(g_hfin + (size_t)p * HD);
    dst[threadIdx.x] = src[threadIdx.x];
}

// ---------------------------------------------------------------------------
// Maxpool over paths (permutation-invariant)
// ---------------------------------------------------------------------------
__global__ void pool_kernel() {
    int j = blockIdx.x * blockDim.x + threadIdx.x;   // 8 x 128
    float m = -3.402823466e+38f;
#pragma unroll 4
    for (int p = 0; p < PN; p++) m = fmaxf(m, g_attn[p * HD + j]);
    g_pooled[j] = m;
}

// ---------------------------------------------------------------------------
// Final linear + sigmoid
// ---------------------------------------------------------------------------
__global__ void final_kernel(const float* __restrict__ Wlin,
                             const float* __restrict__ blin,
                             float* __restrict__ out)
{
    __shared__ float red0[8], red1[8];
    int tid = threadIdx.x;                      // 256
    float s0 = 0.0f, s1 = 0.0f;
    for (int j = tid; j < HD; j += 256) {
        float pv = g_pooled[j];
        s0 += pv * Wlin[j];
        s1 += pv * Wlin[HD + j];
    }
#pragma unroll
    for (int o = 16; o; o >>= 1) {
        s0 += __shfl_xor_sync(0xFFFFFFFFu, s0, o);
        s1 += __shfl_xor_sync(0xFFFFFFFFu, s1, o);
    }
    if ((tid & 31) == 0) { red0[tid >> 5] = s0; red1[tid >> 5] = s1; }
    __syncthreads();
    if (tid == 0) {
        float z0 = blin[0], z1 = blin[1];
#pragma unroll
        for (int w = 0; w < 8; w++) { z0 += red0[w]; z1 += red1[w]; }
        out[0] = 1.0f / (1.0f + expf(-z0));
        out[1] = 1.0f / (1.0f + expf(-z1));
    }
}

// ---------------------------------------------------------------------------
// Launch (same order as round 7 for profile comparability)
// ---------------------------------------------------------------------------
extern "C" void kernel_launch(void* const* d_in, const int* in_sizes, int n_in,
                              void* d_out, int out_size)
{
    (void)in_sizes; (void)n_in; (void)out_size;
    const int*   paths   = (const int*)  d_in[0];
    const int*   lengths = (const int*)  d_in[1];
    const float* emb     = (const float*)d_in[2];
    const float* W_ih    = (const float*)d_in[3];
    const float* W_hh    = (const float*)d_in[4];
    const float* b_ih    = (const float*)d_in[5];
    const float* b_hh    = (const float*)d_in[6];
    const float* W_in    = (const float*)d_in[7];
    const float* b_in    = (const float*)d_in[8];
    const float* W_out   = (const float*)d_in[9];
    const float* b_out   = (const float*)d_in[10];
    const float* W_lin   = (const float*)d_in[11];
    const float* b_lin   = (const float*)d_in[12];
    float* out = (float*)d_out;

    prep_kernel<<<401, 256>>>(lengths, b_ih, b_hh);
    cvt_all_kernel<<<8192, 256>>>(W_ih, W_hh, W_in, W_out);
    gather_kernel<<<LN * PN, 64>>>(paths, emb);
    gemm_bf16<<<dim3(G4 / 64, (PN * LN) / 128), 256>>>(
        nullptr, /*selA*/0, /*selB*/0, /*selC*/0, /*skip*/1, PN * LN, G4, ID);

    for (int t = 0; t < LN; t++)
        lstm_step_kernel<<<dim3(32, 4), 256>>>(t);

    collect_kernel<<<PN, 128>>>();

    gemm_bf16<<<dim3(HD / 64, PN / 128), 256>>>(
        b_in + 2 * HD, /*selA*/1, /*selB*/1, /*selC*/1, /*skip*/0, PN, HD, HD);
    gemm_bf16<<<dim3(HD / 64, PN / 128), 256>>>(
        b_out, /*selA*/2, /*selB*/2, /*selC*/2, /*skip*/0, PN, HD, HD);

    pool_kernel<<<8, 128>>>();
    final_kernel<<<1, 256>>>(W_lin, b_lin, out);
}

// round 12
// speedup vs baseline: 4.9359x; 1.1443x over previous
#include <cuda_runtime.h>
#include <cuda_bf16.h>
#include <cstdint>

// Problem constants
#define PN   256      // num paths
#define LN   64       // max path length
#define ID   512      // input dim
#define HD   1024     // hidden dim
#define G4   4096     // 4*H

// ---------------------------------------------------------------------------
// Scratch (device globals; allocation-free). NEVER passed from host code.
// ---------------------------------------------------------------------------
__device__ __align__(16) __nv_bfloat16 g_x[(size_t)LN * PN * ID];      // gathered emb (sorted p)
__device__ __align__(16) __nv_bfloat16 g_xproj[(size_t)LN * PN * G4];  // [t][ps][4H]
__device__ __align__(16) __nv_bfloat16 g_wih[G4 * ID];
__device__ __align__(16) __nv_bfloat16 g_whh[G4 * HD];
__device__ __align__(16) __nv_bfloat16 g_wv[HD * HD];
__device__ __align__(16) __nv_bfloat16 g_wo[HD * HD];
__device__ __align__(16) __nv_bfloat16 g_h[2][PN * HD];                // double-buffered h (bf16)
__device__ __align__(16) __nv_bfloat16 g_hfin[PN * HD];                // final h per path
__device__ __align__(16) float         g_c[PN * HD];                   // cell state fp32
__device__ __align__(16) float         g_gates[4][PN * G4];            // split-K partials (16MB)
__device__ __align__(16) __nv_bfloat16 g_ctx[PN * HD];
__device__ __align__(16) float         g_attn[PN * HD];
__device__ __align__(16) float         g_bias[G4];                     // b_ih + b_hh
__device__ __align__(16) float         g_pooled[HD];
__device__ int g_perm[PN];
__device__ int g_slen[PN];       // sorted lengths (desc)
__device__ int g_activeM[LN];    // #paths with len > t

// ---------------------------------------------------------------------------
// Helpers
// ---------------------------------------------------------------------------
__device__ __forceinline__ uint32_t cvta_s(const void* p) {
    return (uint32_t)__cvta_generic_to_shared(p);
}
__device__ __forceinline__ void cp_cg16(uint32_t d, const void* s) {
    asm volatile("cp.async.cg.shared.global [%0],[%1],16;\n" :: "r"(d), "l"(s));
}
__device__ __forceinline__ void cp_commit() { asm volatile("cp.async.commit_group;\n"); }
__device__ __forceinline__ void cp_wait0()  { asm volatile("cp.async.wait_group 0;\n"); }
__device__ __forceinline__ void cp_wait1()  { asm volatile("cp.async.wait_group 1;\n"); }

__device__ __forceinline__ void ldsm_x4(uint32_t& r0, uint32_t& r1, uint32_t& r2, uint32_t& r3,
                                        uint32_t addr) {
    asm volatile("ldmatrix.sync.aligned.m8n8.x4.shared.b16 {%0,%1,%2,%3}, [%4];\n"
                 : "=r"(r0), "=r"(r1), "=r"(r2), "=r"(r3) : "r"(addr));
}

__device__ __forceinline__ void mma_bf16(float* c,
                                         uint32_t a0, uint32_t a1, uint32_t a2, uint32_t a3,
                                         uint32_t b0, uint32_t b1) {
    asm volatile(
        "mma.sync.aligned.m16n8k16.row.col.f32.bf16.bf16.f32 "
        "{%0,%1,%2,%3}, {%4,%5,%6,%7}, {%8,%9}, {%0,%1,%2,%3};\n"
        : "+f"(c[0]), "+f"(c[1]), "+f"(c[2]), "+f"(c[3])
        : "r"(a0), "r"(a1), "r"(a2), "r"(a3), "r"(b0), "r"(b1));
}

__device__ __forceinline__ uint32_t packbf2(float lo, float hi) {
    uint32_t r;
    asm("cvt.rn.bf16x2.f32 %0, %1, %2;\n" : "=r"(r) : "f"(hi), "f"(lo));
    return r;
}
__device__ __forceinline__ float bflo(uint32_t u) { return __uint_as_float(u << 16); }
__device__ __forceinline__ float bfhi(uint32_t u) { return __uint_as_float(u & 0xFFFF0000u); }

__device__ __forceinline__ float fast_tanh(float x) {
    float y; asm("tanh.approx.f32 %0,%1;\n" : "=f"(y) : "f"(x)); return y;
}
__device__ __forceinline__ float fsig(float x) { return 0.5f * fast_tanh(0.5f * x) + 0.5f; }

// ldmatrix offsets for 20-word (80B) padded rows
__device__ __forceinline__ int ldsm_a_off(int lane) {
    return ((lane & 15) * 20 + (lane >> 4) * 4) * 4;
}
__device__ __forceinline__ int ldsm_b_off(int lane) {
    return ((lane & 7) * 20 + ((lane >> 3) & 1) * 4 + ((lane >> 4) & 1) * 160) * 4;
}

// ---------------------------------------------------------------------------
// Fused prep+cvt. Grid 8593 x 256.
// ---------------------------------------------------------------------------
__global__ void prepcvt_kernel(const int* __restrict__ lengths,
                               const float* __restrict__ b_ih,
                               const float* __restrict__ b_hh,
                               const float* __restrict__ Wih,
                               const float* __restrict__ Whh,
                               const float* __restrict__ Win,
                               const float* __restrict__ Wout) {
    int b = blockIdx.x, tid = threadIdx.x;
    if (b == 0) {
        __shared__ int s_cnt[LN + 1];
        __shared__ int s_start[LN + 1];
        if (tid <= LN) s_cnt[tid] = 0;
        __syncthreads();
        if (tid < PN) atomicAdd(&s_cnt[lengths[tid]], 1);
        __syncthreads();
        if (tid == 0) {
            int run = 0;
            for (int l = LN; l >= 1; l--) { s_start[l] = run; run += s_cnt[l]; }
            for (int p = 0; p < PN; p++) { int l = lengths[p]; g_perm[s_start[l]++] = p; }
        }
        __syncthreads();
        if (tid < PN) g_slen[tid] = lengths[g_perm[tid]];
        if (tid < LN) {
            int a = 0;
            for (int l = tid + 1; l <= LN; l++) a += s_cnt[l];
            g_activeM[tid] = a;
        }
    } else if (b <= 384) {
        int i = (b - 1) * 256 + tid;
        uint4 z = make_uint4(0u, 0u, 0u, 0u);
        if (i < 65536)      reinterpret_cast<uint4*>(g_c)[i] = z;
        else if (i < 98304) reinterpret_cast<uint4*>(g_h[0])[i - 65536] = z;
    } else if (b <= 400) {
        int i = (b - 385) * 256 + tid;
        g_bias[i] = b_ih[i] + b_hh[i];
    } else {
        int gid = (b - 401) * 256 + tid;
        const float* src; __nv_bfloat16* dst; int off;
        if (gid < 524288)       { src = Wih;  dst = g_wih; off = gid; }
        else if (gid < 1572864) { src = Whh;  dst = g_whh; off = gid - 524288; }
        else if (gid < 1835008) { src = Win + (size_t)2 * HD * HD; dst = g_wv; off = gid - 1572864; }
        else                    { src = Wout; dst = g_wo;  off = gid - 1835008; }
        int i = off * 4;
        float4 v = *reinterpret_cast<const float4*>(src + i);
        *reinterpret_cast<uint2*>(dst + i) = make_uint2(packbf2(v.x, v.y), packbf2(v.z, v.w));
    }
}

// ---------------------------------------------------------------------------
// Gather + convert
// ---------------------------------------------------------------------------
__global__ void gather_kernel(const int* __restrict__ paths, const float* __restrict__ emb) {
    int m = blockIdx.x;
    int t = m >> 8, ps = m & 255;
    if (t >= g_slen[ps]) return;
    int tok = paths[g_perm[ps] * LN + t];
    const float4* src = reinterpret_cast<const float4*>(emb + (size_t)tok * ID);
    int tid = threadIdx.x;   // 64
    float4 v0 = src[tid * 2], v1 = src[tid * 2 + 1];
    uint4 o;
    o.x = packbf2(v0.x, v0.y); o.y = packbf2(v0.z, v0.w);
    o.z = packbf2(v1.x, v1.y); o.w = packbf2(v1.z, v1.w);
    reinterpret_cast<uint4*>(g_x + (size_t)m * ID)[tid] = o;
}

// ---------------------------------------------------------------------------
// bf16 GEMM (proven): ldmatrix + 3-stage cp.async. BM=128 BN=64 BK=32.
// ---------------------------------------------------------------------------
#define GA_STAGE 10240
#define GB_STAGE 5120

__global__ __launch_bounds__(256)
void gemm_bf16(const float* __restrict__ bias,
               int selA, int selB, int selC, int skipMode,
               int M, int N, int K)
{
    __shared__ uint32_t As[3][128 * 20];
    __shared__ uint32_t Bs[3][64 * 20];

    const int tid = threadIdx.x, warp = tid >> 5, lane = tid & 31;
    const int wm = warp >> 1, wn = warp & 1;
    const int m0 = blockIdx.y * 128, n0 = blockIdx.x * 64;

    if (skipMode) {
        int t = m0 >> 8, ps0 = m0 & 255;
        if (g_activeM[t] <= ps0) return;
    }

    const __nv_bfloat16* A = g_x;
    if (selA == 1) A = g_hfin;
    else if (selA == 2) A = g_ctx;
    const __nv_bfloat16* B = g_wih;
    if (selB == 1) B = g_wv;
    else if (selB == 2) B = g_wo;

    float acc[2][4][4];
#pragma unroll
    for (int i = 0; i < 2; i++)
#pragma unroll
        for (int j = 0; j < 4; j++)
#pragma unroll
            for (int q = 0; q < 4; q++) acc[i][j][q] = 0.0f;

    const int nk = K >> 5;
    const uint32_t a_base = cvta_s(As);
    const uint32_t b_base = cvta_s(Bs);
    const int lrow = tid >> 2, lc = tid & 3;
    const int aoff = ldsm_a_off(lane), boff = ldsm_b_off(lane);

#pragma unroll
    for (int s = 0; s < 2; s++) {
        int k0 = s * 32;
        uint32_t ab = a_base + s * GA_STAGE, bb_ = b_base + s * GB_STAGE;
        cp_cg16(ab + (lrow * 20 + lc * 4) * 4,        A + (size_t)(m0 + lrow) * K + k0 + lc * 8);
        cp_cg16(ab + ((lrow + 64) * 20 + lc * 4) * 4, A + (size_t)(m0 + lrow + 64) * K + k0 + lc * 8);
        cp_cg16(bb_ + (lrow * 20 + lc * 4) * 4,       B + (size_t)(n0 + lrow) * K + k0 + lc * 8);
        cp_commit();
    }

    for (int kt = 0; kt < nk; kt++) {
        if (kt + 1 < nk) cp_wait1(); else cp_wait0();
        __syncthreads();

        if (kt + 2 < nk) {
            int s = (kt + 2) % 3, k0 = (kt + 2) * 32;
            uint32_t ab = a_base + s * GA_STAGE, bb_ = b_base + s * GB_STAGE;
            cp_cg16(ab + (lrow * 20 + lc * 4) * 4,        A + (size_t)(m0 + lrow) * K + k0 + lc * 8);
            cp_cg16(ab + ((lrow + 64) * 20 + lc * 4) * 4, A + (size_t)(m0 + lrow + 64) * K + k0 + lc * 8);
            cp_cg16(bb_ + (lrow * 20 + lc * 4) * 4,       B + (size_t)(n0 + lrow) * K + k0 + lc * 8);
            cp_commit();
        }

        const uint32_t asc = a_base + (kt % 3) * GA_STAGE;
        const uint32_t bsc = b_base + (kt % 3) * GB_STAGE;
#pragma unroll
        for (int ks = 0; ks < 2; ks++) {
            const int kby = ks * 32;
            uint32_t a0[2], a1[2], a2[2], a3[2];
#pragma unroll
            for (int mi = 0; mi < 2; mi++)
                ldsm_x4(a0[mi], a1[mi], a2[mi], a3[mi],
                        asc + (wm * 32 + mi * 16) * 80 + kby + aoff);
            uint32_t bb[8];
#pragma unroll
            for (int njp = 0; njp < 2; njp++)
                ldsm_x4(bb[njp * 4], bb[njp * 4 + 1], bb[njp * 4 + 2], bb[njp * 4 + 3],
                        bsc + (wn * 32 + njp * 16) * 80 + kby + boff);
#pragma unroll
            for (int nj = 0; nj < 4; nj++) {
                uint32_t b0 = bb[(nj >> 1) * 4 + (nj & 1) * 2];
                uint32_t b1 = bb[(nj >> 1) * 4 + (nj & 1) * 2 + 1];
                mma_bf16(acc[0][nj], a0[0], a1[0], a2[0], a3[0], b0, b1);
                mma_bf16(acc[1][nj], a0[1], a1[1], a2[1], a3[1], b0, b1);
            }
        }
    }

#pragma unroll
    for (int mi = 0; mi < 2; mi++) {
#pragma unroll
        for (int half = 0; half < 2; half++) {
            int row = m0 + wm * 32 + mi * 16 + (lane >> 2) + half * 8;
#pragma unroll
            for (int nj = 0; nj < 4; nj++) {
                int col = n0 + wn * 32 + nj * 8 + 2 * (lane & 3);
                float v0 = acc[mi][nj][half * 2];
                float v1 = acc[mi][nj][half * 2 + 1];
                if (bias) { v0 += bias[col]; v1 += bias[col + 1]; }
                if (selC == 2) {
                    g_attn[(size_t)row * N + col]     = v0;
                    g_attn[(size_t)row * N + col + 1] = v1;
                } else {
                    __nv_bfloat16* C = (selC == 0) ? g_xproj : g_ctx;
                    *reinterpret_cast<uint32_t*>(C + (size_t)row * N + col) = packbf2(v0, v1);
                }
            }
        }
    }
}

// ---------------------------------------------------------------------------
// LSTM matmul with split-K. Grid (32 n-tiles, 4 p-tiles, 4 k-chunks) x 256.
// Block: M=64 p-rows x N=128 Whh-rows (flat [4096] = torch gate layout),
// K=256 chunk at kOff = z*256. Writes fp32 partials to g_gates[z] (active
// rows only). 8 kt iterations of BK=32 with 3-stage cp.async.
// ---------------------------------------------------------------------------
#define LH_STAGE 5120      // 64 rows x 80 B
#define LW_STAGE 10240     // 128 rows x 80 B

__global__ __launch_bounds__(256)
void lstm_mm(int t)
{
    __shared__ uint32_t SM[11520];     // 3 x (1280 + 2560) words = 46 KB
    const int activeM = g_activeM[t];
    const int pbase = blockIdx.y * 64;
    if (pbase >= activeM) return;
    const int n0 = blockIdx.x * 128;   // flat Whh row / gate-col base
    const int z = blockIdx.z;
    const int kOff = z * 256;
    const int tid = threadIdx.x, warp = tid >> 5, lane = tid & 31;
    const int wm = warp >> 2, wn = warp & 3;      // 2m x 4n warps, tile 32x32
    const __nv_bfloat16* hin = g_h[t & 1];

    const uint32_t h_base = cvta_s(SM);
    const uint32_t w_base = h_base + 3 * LH_STAGE;

    float acc[2][4][4];
#pragma unroll
    for (int i = 0; i < 2; i++)
#pragma unroll
        for (int j = 0; j < 4; j++)
#pragma unroll
            for (int q = 0; q < 4; q++) acc[i][j][q] = 0.0f;

    const int arow = tid >> 2, ach = tid & 3;
    const int aoff = ldsm_a_off(lane), boff = ldsm_b_off(lane);

#pragma unroll
    for (int s = 0; s < 2; s++) {
        int k0 = kOff + s * 32;
        cp_cg16(h_base + s * LH_STAGE + (arow * 20 + ach * 4) * 4,
                hin + (size_t)(pbase + arow) * HD + k0 + ach * 8);
#pragma unroll
        for (int i = 0; i < 2; i++) {
            int e = tid + i * 256, c = e >> 2, ch = e & 3;
            cp_cg16(w_base + s * LW_STAGE + (c * 20 + ch * 4) * 4,
                    g_whh + (size_t)(n0 + c) * HD + k0 + ch * 8);
        }
        cp_commit();
    }

    for (int kt = 0; kt < 8; kt++) {
        if (kt + 1 < 8) cp_wait1(); else cp_wait0();
        __syncthreads();

        if (kt + 2 < 8) {
            int s = (kt + 2) % 3, k0 = kOff + (kt + 2) * 32;
            cp_cg16(h_base + s * LH_STAGE + (arow * 20 + ach * 4) * 4,
                    hin + (size_t)(pbase + arow) * HD + k0 + ach * 8);
#pragma unroll
            for (int i = 0; i < 2; i++) {
                int e = tid + i * 256, c = e >> 2, ch = e & 3;
                cp_cg16(w_base + s * LW_STAGE + (c * 20 + ch * 4) * 4,
                        g_whh + (size_t)(n0 + c) * HD + k0 + ch * 8);
            }
            cp_commit();
        }

        const uint32_t asc = h_base + (kt % 3) * LH_STAGE;
        const uint32_t bsc = w_base + (kt % 3) * LW_STAGE;
#pragma unroll
        for (int ks = 0; ks < 2; ks++) {
            const int kby = ks * 32;
            uint32_t a0[2], a1[2], a2[2], a3[2];
#pragma unroll
            for (int mi = 0; mi < 2; mi++)
                ldsm_x4(a0[mi], a1[mi], a2[mi], a3[mi],
                        asc + (wm * 32 + mi * 16) * 80 + kby + aoff);
            uint32_t bb[8];
#pragma unroll
            for (int njp = 0; njp < 2; njp++)
                ldsm_x4(bb[njp * 4], bb[njp * 4 + 1], bb[njp * 4 + 2], bb[njp * 4 + 3],
                        bsc + (wn * 32 + njp * 16) * 80 + kby + boff);
#pragma unroll
            for (int nj = 0; nj < 4; nj++) {
                uint32_t b0 = bb[(nj >> 1) * 4 + (nj & 1) * 2];
                uint32_t b1 = bb[(nj >> 1) * 4 + (nj & 1) * 2 + 1];
                mma_bf16(acc[0][nj], a0[0], a1[0], a2[0], a3[0], b0, b1);
                mma_bf16(acc[1][nj], a0[1], a1[1], a2[1], a3[1], b0, b1);
            }
        }
        __syncthreads();
    }

    // epilogue: fp32 partials, active rows only
    float* G = g_gates[z];
#pragma unroll
    for (int mi = 0; mi < 2; mi++) {
#pragma unroll
        for (int half = 0; half < 2; half++) {
            int row = pbase + wm * 32 + mi * 16 + (lane >> 2) + half * 8;
            if (row < activeM) {
#pragma unroll
                for (int nj = 0; nj < 4; nj++) {
                    int col = n0 + wn * 32 + nj * 8 + 2 * (lane & 3);
                    G[(size_t)row * G4 + col]     = acc[mi][nj][half * 2];
                    G[(size_t)row * G4 + col + 1] = acc[mi][nj][half * 2 + 1];
                }
            }
        }
    }
}

// ---------------------------------------------------------------------------
// Pointwise: sum 4 partials + xproj + bias -> gates -> (c,h).
// Grid PN x 256 threads; thread handles 4 j's for all 4 gates.
// Frozen rows (p >= activeM) copy h forward.
// ---------------------------------------------------------------------------
__global__ void pw_kernel(int t)
{
    const int p = blockIdx.x, tid = threadIdx.x;
    const __nv_bfloat16* hin = g_h[t & 1];
    __nv_bfloat16* hout = g_h[(t + 1) & 1];
    if (p >= g_activeM[t]) {
        reinterpret_cast<uint2*>(hout + (size_t)p * HD)[tid] =
            reinterpret_cast<const uint2*>(hin + (size_t)p * HD)[tid];
        return;
    }
    const int j = tid * 4;
    const size_t rowOff = (size_t)p * G4;
    const __nv_bfloat16* xr = g_xproj + (size_t)t * PN * G4 + rowOff;

    float gv[4][4];
#pragma unroll
    for (int g = 0; g < 4; g++) {
        int idx = g * HD + j;
        float4 s0 = *reinterpret_cast<const float4*>(&g_gates[0][rowOff + idx]);
        float4 s1 = *reinterpret_cast<const float4*>(&g_gates[1][rowOff + idx]);
        float4 s2 = *reinterpret_cast<const float4*>(&g_gates[2][rowOff + idx]);
        float4 s3 = *reinterpret_cast<const float4*>(&g_gates[3][rowOff + idx]);
        uint2 xv = *reinterpret_cast<const uint2*>(xr + idx);
        float4 bv = *reinterpret_cast<const float4*>(g_bias + idx);
        gv[g][0] = s0.x + s1.x + s2.x + s3.x + bflo(xv.x) + bv.x;
        gv[g][1] = s0.y + s1.y + s2.y + s3.y + bfhi(xv.x) + bv.y;
        gv[g][2] = s0.z + s1.z + s2.z + s3.z + bflo(xv.y) + bv.z;
        gv[g][3] = s0.w + s1.w + s2.w + s3.w + bfhi(xv.y) + bv.w;
    }
    float* cp = g_c + (size_t)p * HD + j;
    float4 cv = *reinterpret_cast<const float4*>(cp);
    float cc[4] = { cv.x, cv.y, cv.z, cv.w };
    float hh[4];
#pragma unroll
    for (int e = 0; e < 4; e++) {
        float cn = fsig(gv[1][e]) * cc[e] + fsig(gv[0][e]) * fast_tanh(gv[2][e]);
        cc[e] = cn;
        hh[e] = fsig(gv[3][e]) * fast_tanh(cn);
    }
    *reinterpret_cast<float4*>(cp) = make_float4(cc[0], cc[1], cc[2], cc[3]);
    *reinterpret_cast<uint2*>(hout + (size_t)p * HD + j) =
        make_uint2(packbf2(hh[0], hh[1]), packbf2(hh[2], hh[3]));
}

// ---------------------------------------------------------------------------
// Collect final h per path from the parity buffer g_h[len & 1]
// ---------------------------------------------------------------------------
__global__ void collect_kernel() {
    int p = blockIdx.x;
    int parity = g_slen[p] & 1;
    const uint4* src = reinterpret_cast<const uint4*>(g_h[parity] + (size_t)p * HD);
    uint4* dst = reinterpret_cast<uint4*>(g_hfin + (size_t)p * HD);
    dst[threadIdx.x] = src[threadIdx.x];
}

// ---------------------------------------------------------------------------
// Maxpool over paths
// ---------------------------------------------------------------------------
__global__ void pool_kernel() {
    int j = blockIdx.x * blockDim.x + threadIdx.x;
    float m = -3.402823466e+38f;
#pragma unroll 4
    for (int p = 0; p < PN; p++) m = fmaxf(m, g_attn[p * HD + j]);
    g_pooled[j] = m;
}

// ---------------------------------------------------------------------------
// Final linear + sigmoid
// ---------------------------------------------------------------------------
__global__ void final_kernel(const float* __restrict__ Wlin,
                             const float* __restrict__ blin,
                             float* __restrict__ out)
{
    __shared__ float red0[8], red1[8];
    int tid = threadIdx.x;
    float s0 = 0.0f, s1 = 0.0f;
    for (int j = tid; j < HD; j += 256) {
        float pv = g_pooled[j];
        s0 += pv * Wlin[j];
        s1 += pv * Wlin[HD + j];
    }
#pragma unroll
    for (int o = 16; o; o >>= 1) {
        s0 += __shfl_xor_sync(0xFFFFFFFFu, s0, o);
        s1 += __shfl_xor_sync(0xFFFFFFFFu, s1, o);
    }
    if ((tid & 31) == 0) { red0[tid >> 5] = s0; red1[tid >> 5] = s1; }
    __syncthreads();
    if (tid == 0) {
        float z0 = blin[0], z1 = blin[1];
#pragma unroll
        for (int w = 0; w < 8; w++) { z0 += red0[w]; z1 += red1[w]; }
        out[0] = 1.0f / (1.0f + expf(-z0));
        out[1] = 1.0f / (1.0f + expf(-z1));
    }
}

// ---------------------------------------------------------------------------
// Launch. Order: prepcvt(0) gather(1) xproj(2) mm t0(3) pw t0(4) mm t1(5)
// -> ncu idx 5 profiles lstm_mm.
// ---------------------------------------------------------------------------
extern "C" void kernel_launch(void* const* d_in, const int* in_sizes, int n_in,
                              void* d_out, int out_size)
{
    (void)in_sizes; (void)n_in; (void)out_size;
    const int*   paths   = (const int*)  d_in[0];
    const int*   lengths = (const int*)  d_in[1];
    const float* emb     = (const float*)d_in[2];
    const float* W_ih    = (const float*)d_in[3];
    const float* W_hh    = (const float*)d_in[4];
    const float* b_ih    = (const float*)d_in[5];
    const float* b_hh    = (const float*)d_in[6];
    const float* W_in    = (const float*)d_in[7];
    const float* b_in    = (const float*)d_in[8];
    const float* W_out   = (const float*)d_in[9];
    const float* b_out   = (const float*)d_in[10];
    const float* W_lin   = (const float*)d_in[11];
    const float* b_lin   = (const float*)d_in[12];
    float* out = (float*)d_out;

    prepcvt_kernel<<<8593, 256>>>(lengths, b_ih, b_hh, W_ih, W_hh, W_in, W_out);
    gather_kernel<<<LN * PN, 64>>>(paths, emb);
    gemm_bf16<<<dim3(G4 / 64, (PN * LN) / 128), 256>>>(
        nullptr, /*selA*/0, /*selB*/0, /*selC*/0, /*skip*/1, PN * LN, G4, ID);

    for (int t = 0; t < LN; t++) {
        lstm_mm<<<dim3(32, 4, 4), 256>>>(t);
        pw_kernel<<<PN, 256>>>(t);
    }

    collect_kernel<<<PN, 128>>>();

    gemm_bf16<<<dim3(HD / 64, PN / 128), 256>>>(
        b_in + 2 * HD, /*selA*/1, /*selB*/1, /*selC*/1, /*skip*/0, PN, HD, HD);
    gemm_bf16<<<dim3(HD / 64, PN / 128), 256>>>(
        b_out, /*selA*/2, /*selB*/2, /*selC*/2, /*skip*/0, PN, HD, HD);

    pool_kernel<<<8, 128>>>();
    final_kernel<<<1, 256>>>(W_lin, b_lin, out);
}